// round 1
// baseline (speedup 1.0000x reference)
#include <cuda_runtime.h>
#include <math.h>
#include <math_constants.h>

// Problem constants
#define BB 2
#define SS 2048
#define DD 1024
#define HH 16
#define DHH 64

// Scratch (no cudaMalloc allowed): QKV activations and attention output
__device__ float g_qkv[(size_t)BB * SS * 3 * DD];   // [4096][3072]
__device__ float g_attn[(size_t)BB * SS * DD];      // [4096][1024]

// ---------------------------------------------------------------------------
// SGEMM "NT": C[m,n] = sum_k A[m,k] * B[n,k]
// A: [M,K] row-major, B: [N,K] row-major, C: [M,N] row-major.
// 128x128 block tile, BK=16, 256 threads, 8x8 per-thread microtile.
// M,N multiples of 128; K multiple of 16 (true for all our shapes).
// ---------------------------------------------------------------------------
__global__ __launch_bounds__(256) void sgemm_nt(const float* __restrict__ A,
                                                const float* __restrict__ Bm,
                                                float* __restrict__ C,
                                                int M, int N, int K)
{
    __shared__ float As[16][132];
    __shared__ float Bs[16][132];

    const int tid = threadIdx.x;
    const int bm = blockIdx.y * 128;
    const int bn = blockIdx.x * 128;
    const int ty = tid >> 4;          // 0..15 -> row group
    const int tx = tid & 15;          // 0..15 -> col group
    const int lrow = tid >> 2;        // 0..63
    const int lcol = (tid & 3) << 2;  // 0,4,8,12

    float acc[8][8];
#pragma unroll
    for (int i = 0; i < 8; i++)
#pragma unroll
        for (int j = 0; j < 8; j++) acc[i][j] = 0.f;

    for (int k0 = 0; k0 < K; k0 += 16) {
#pragma unroll
        for (int half = 0; half < 2; half++) {
            int r = lrow + half * 64;
            float4 va = *(const float4*)(A + (size_t)(bm + r) * K + k0 + lcol);
            As[lcol + 0][r] = va.x;
            As[lcol + 1][r] = va.y;
            As[lcol + 2][r] = va.z;
            As[lcol + 3][r] = va.w;
            float4 vb = *(const float4*)(Bm + (size_t)(bn + r) * K + k0 + lcol);
            Bs[lcol + 0][r] = vb.x;
            Bs[lcol + 1][r] = vb.y;
            Bs[lcol + 2][r] = vb.z;
            Bs[lcol + 3][r] = vb.w;
        }
        __syncthreads();

#pragma unroll
        for (int k = 0; k < 16; k++) {
            float a[8], b[8];
            *(float4*)&a[0] = *(const float4*)&As[k][ty * 8];
            *(float4*)&a[4] = *(const float4*)&As[k][ty * 8 + 4];
            *(float4*)&b[0] = *(const float4*)&Bs[k][tx * 8];
            *(float4*)&b[4] = *(const float4*)&Bs[k][tx * 8 + 4];
#pragma unroll
            for (int i = 0; i < 8; i++)
#pragma unroll
                for (int j = 0; j < 8; j++)
                    acc[i][j] = fmaf(a[i], b[j], acc[i][j]);
        }
        __syncthreads();
    }

#pragma unroll
    for (int i = 0; i < 8; i++) {
        float* cp = C + (size_t)(bm + ty * 8 + i) * N + bn + tx * 8;
        float4 v0 = {acc[i][0], acc[i][1], acc[i][2], acc[i][3]};
        float4 v1 = {acc[i][4], acc[i][5], acc[i][6], acc[i][7]};
        *(float4*)cp = v0;
        *(float4*)(cp + 4) = v1;
    }
}

// ---------------------------------------------------------------------------
// Causal flash attention, fp32. One block per (q-tile of 64 rows, head, batch).
// 256 threads: 4 threads per q-row (quad), each quad-lane owns 16 of dh=64.
// QKV layout: g_qkv[(b*S+s)*3072 + {0,1024,2048} + h*64 + d]
// Output to g_attn[(b*S+s)*1024 + h*64 + d]
// ---------------------------------------------------------------------------
__global__ __launch_bounds__(256) void attn_kernel()
{
    __shared__ float Ks[64][64];
    __shared__ float Vs[64][64];
    __shared__ float Sc[64][64];  // Sc[k][r] : scores, k-major to avoid bank conflicts

    const int qt = blockIdx.x;   // 0..31
    const int h  = blockIdx.y;   // 0..15
    const int b  = blockIdx.z;   // 0..1
    const int tid = threadIdx.x;
    const int r  = tid >> 2;     // q-row within tile, 0..63
    const int l4 = tid & 3;      // quad lane, 0..3
    const int qrow = qt * 64 + r;

    const float* base = g_qkv + (size_t)b * SS * (3 * DD);

    // Q slice in registers: 16 floats of this q-row
    float q[16];
    {
        const float* qp = base + (size_t)qrow * 3072 + h * 64 + l4 * 16;
#pragma unroll
        for (int i = 0; i < 16; i += 4)
            *(float4*)&q[i] = *(const float4*)(qp + i);
    }

    float o[16];
#pragma unroll
    for (int i = 0; i < 16; i++) o[i] = 0.f;
    float mrun = -CUDART_INF_F;
    float lsum = 0.f;

    const int kr = tid >> 2;          // load row
    const int c0 = (tid & 3) * 16;    // load col base

    for (int kt = 0; kt <= qt; kt++) {
        // Load K and V tiles (64x64 each), fully coalesced float4
        {
            const float* kp = base + (size_t)(kt * 64 + kr) * 3072 + 1024 + h * 64 + c0;
            const float* vp = kp + 1024;
#pragma unroll
            for (int i = 0; i < 16; i += 4) {
                *(float4*)&Ks[kr][c0 + i] = *(const float4*)(kp + i);
                *(float4*)&Vs[kr][c0 + i] = *(const float4*)(vp + i);
            }
        }
        __syncthreads();

        // Scores: each quad computes full 64-wide dot per k via shuffle reduce
        float tilemax = -CUDART_INF_F;
        const bool diag = (kt == qt);
#pragma unroll 4
        for (int k = 0; k < 64; k++) {
            float s = 0.f;
#pragma unroll
            for (int i = 0; i < 16; i++)
                s = fmaf(q[i], Ks[k][l4 * 16 + i], s);
            s += __shfl_xor_sync(0xffffffffu, s, 1);
            s += __shfl_xor_sync(0xffffffffu, s, 2);
            s *= 0.125f;  // 1/sqrt(64)
            if (diag && k > r) s = -CUDART_INF_F;
            tilemax = fmaxf(tilemax, s);
            if (l4 == 0) Sc[k][r] = s;
        }
        __syncwarp();

        // Online softmax update
        float mnew = fmaxf(mrun, tilemax);
        float corr = __expf(mrun - mnew);  // 0 on first tile (exp(-inf))
        lsum *= corr;
#pragma unroll
        for (int i = 0; i < 16; i++) o[i] *= corr;

#pragma unroll 2
        for (int k = 0; k < 64; k++) {
            float p = __expf(Sc[k][r] - mnew);
            lsum += p;
#pragma unroll
            for (int i = 0; i < 16; i++)
                o[i] = fmaf(p, Vs[k][l4 * 16 + i], o[i]);
        }
        mrun = mnew;
        __syncthreads();
    }

    const float inv = 1.f / lsum;
    float* op = g_attn + (size_t)(b * SS + qrow) * DD + h * 64 + l4 * 16;
#pragma unroll
    for (int i = 0; i < 16; i += 4) {
        float4 v = {o[i] * inv, o[i + 1] * inv, o[i + 2] * inv, o[i + 3] * inv};
        *(float4*)(op + i) = v;
    }
}

// ---------------------------------------------------------------------------
// Launch: QKV GEMM -> causal flash attention -> output projection GEMM
// ---------------------------------------------------------------------------
extern "C" void kernel_launch(void* const* d_in, const int* in_sizes, int n_in,
                              void* d_out, int out_size)
{
    const float* x   = (const float*)d_in[0];  // [2,2048,1024]
    const float* wqkv = (const float*)d_in[1]; // [3072,1024]
    const float* wo  = (const float*)d_in[2];  // [1024,1024]
    float* out = (float*)d_out;                // [2,2048,1024]

    float *pq = nullptr, *pa = nullptr;
    cudaGetSymbolAddress((void**)&pq, g_qkv);
    cudaGetSymbolAddress((void**)&pa, g_attn);

    // QKV = x @ wqkv^T : M=4096, N=3072, K=1024
    sgemm_nt<<<dim3(3072 / 128, 4096 / 128), 256>>>(x, wqkv, pq, 4096, 3072, 1024);

    // Attention: grid (q-tiles, heads, batch)
    attn_kernel<<<dim3(SS / 64, HH, BB), 256>>>();

    // out = attn @ wo^T : M=4096, N=1024, K=1024
    sgemm_nt<<<dim3(1024 / 128, 4096 / 128), 256>>>(pa, wo, out, 4096, 1024, 1024);
}

// round 2
// speedup vs baseline: 2.3198x; 2.3198x over previous
#include <cuda_runtime.h>
#include <math.h>
#include <math_constants.h>

// Problem constants
#define BB 2
#define SS 2048
#define DD 1024
#define HH 16
#define DHH 64

// Scratch (no cudaMalloc allowed)
__device__ float g_qkv[(size_t)BB * SS * 3 * DD];   // [4096][3072]
__device__ float g_attn[(size_t)BB * SS * DD];      // [4096][1024]

// ---------------------------------------------------------------------------
// SGEMM "NT": C[m,n] = sum_k A[m,k] * B[n,k]
// ---------------------------------------------------------------------------
__global__ __launch_bounds__(256) void sgemm_nt(const float* __restrict__ A,
                                                const float* __restrict__ Bm,
                                                float* __restrict__ C,
                                                int M, int N, int K)
{
    __shared__ float As[16][132];
    __shared__ float Bs[16][132];

    const int tid = threadIdx.x;
    const int bm = blockIdx.y * 128;
    const int bn = blockIdx.x * 128;
    const int ty = tid >> 4;
    const int tx = tid & 15;
    const int lrow = tid >> 2;
    const int lcol = (tid & 3) << 2;

    float acc[8][8];
#pragma unroll
    for (int i = 0; i < 8; i++)
#pragma unroll
        for (int j = 0; j < 8; j++) acc[i][j] = 0.f;

    for (int k0 = 0; k0 < K; k0 += 16) {
#pragma unroll
        for (int half = 0; half < 2; half++) {
            int r = lrow + half * 64;
            float4 va = *(const float4*)(A + (size_t)(bm + r) * K + k0 + lcol);
            As[lcol + 0][r] = va.x;
            As[lcol + 1][r] = va.y;
            As[lcol + 2][r] = va.z;
            As[lcol + 3][r] = va.w;
            float4 vb = *(const float4*)(Bm + (size_t)(bn + r) * K + k0 + lcol);
            Bs[lcol + 0][r] = vb.x;
            Bs[lcol + 1][r] = vb.y;
            Bs[lcol + 2][r] = vb.z;
            Bs[lcol + 3][r] = vb.w;
        }
        __syncthreads();

#pragma unroll
        for (int k = 0; k < 16; k++) {
            float a[8], b[8];
            *(float4*)&a[0] = *(const float4*)&As[k][ty * 8];
            *(float4*)&a[4] = *(const float4*)&As[k][ty * 8 + 4];
            *(float4*)&b[0] = *(const float4*)&Bs[k][tx * 8];
            *(float4*)&b[4] = *(const float4*)&Bs[k][tx * 8 + 4];
#pragma unroll
            for (int i = 0; i < 8; i++)
#pragma unroll
                for (int j = 0; j < 8; j++)
                    acc[i][j] = fmaf(a[i], b[j], acc[i][j]);
        }
        __syncthreads();
    }

#pragma unroll
    for (int i = 0; i < 8; i++) {
        float* cp = C + (size_t)(bm + ty * 8 + i) * N + bn + tx * 8;
        float4 v0 = {acc[i][0], acc[i][1], acc[i][2], acc[i][3]};
        float4 v1 = {acc[i][4], acc[i][5], acc[i][6], acc[i][7]};
        *(float4*)cp = v0;
        *(float4*)(cp + 4) = v1;
    }
}

// ---------------------------------------------------------------------------
// Register-tiled causal flash attention, fp32.
// Block: 128 q-rows x (one head, one batch). 256 threads = 16(ty) x 16(tx).
// Per k-tile of 64: S microtile 8x4 per thread (rows=ty*8.., cols=tx*4..),
// softmax in registers with shfl reductions across tx, P staged via SMEM,
// O microtile 8x4 (same rows, d-cols=tx*4..).
// ---------------------------------------------------------------------------
__global__ __launch_bounds__(256, 2) void attn_kernel()
{
    extern __shared__ float sm[];
    float* Qs = sm;               // [64 d][132]  Qs[d*132 + r]
    float* Ks = Qs + 64 * 132;    // [64 d][68]   Ks[d*68 + k]
    float* Vs = Ks + 64 * 68;     // [64 k][68]   Vs[k*68 + d]
    float* Ps = Vs + 64 * 68;     // [128 r][68]  Ps[r*68 + k]

    const int qt = (int)gridDim.x - 1 - (int)blockIdx.x;  // heavy tiles first
    const int h = blockIdx.y;
    const int b = blockIdx.z;
    const int tid = threadIdx.x;
    const int ty = tid >> 4;
    const int tx = tid & 15;

    const float* base = g_qkv + (size_t)b * SS * 3072;

    // Load Q tile transposed into Qs[d][r]
    {
        const int lr = tid >> 1;           // 0..127
        const int c0 = (tid & 1) * 32;     // 0 or 32
        const float* qp = base + (size_t)(qt * 128 + lr) * 3072 + h * 64 + c0;
#pragma unroll
        for (int f = 0; f < 8; f++) {
            float4 v = *(const float4*)(qp + f * 4);
            int d = c0 + f * 4;
            Qs[(d + 0) * 132 + lr] = v.x;
            Qs[(d + 1) * 132 + lr] = v.y;
            Qs[(d + 2) * 132 + lr] = v.z;
            Qs[(d + 3) * 132 + lr] = v.w;
        }
    }

    float m[8], l[8], o[8][4];
#pragma unroll
    for (int i = 0; i < 8; i++) {
        m[i] = -CUDART_INF_F;
        l[i] = 0.f;
#pragma unroll
        for (int j = 0; j < 4; j++) o[i][j] = 0.f;
    }

    const int kr = tid >> 2;          // 0..63
    const int kc0 = (tid & 3) * 16;   // 0,16,32,48
    const int nkt = 2 * qt + 2;

    for (int kt = 0; kt < nkt; kt++) {
        __syncthreads();  // previous O-GEMM done reading Vs/Ps (and covers nothing on iter 0)

        // Load K (transposed) and V tiles
        {
            const float* kp = base + (size_t)(kt * 64 + kr) * 3072 + 1024 + h * 64 + kc0;
            const float* vp = kp + 1024;
#pragma unroll
            for (int f = 0; f < 4; f++) {
                float4 kv = *(const float4*)(kp + f * 4);
                int d = kc0 + f * 4;
                Ks[(d + 0) * 68 + kr] = kv.x;
                Ks[(d + 1) * 68 + kr] = kv.y;
                Ks[(d + 2) * 68 + kr] = kv.z;
                Ks[(d + 3) * 68 + kr] = kv.w;
                *(float4*)(Vs + kr * 68 + d) = *(const float4*)(vp + f * 4);
            }
        }
        __syncthreads();

        // S = Q @ K^T  (8x4 microtile in registers)
        float s[8][4];
#pragma unroll
        for (int i = 0; i < 8; i++)
#pragma unroll
            for (int j = 0; j < 4; j++) s[i][j] = 0.f;

#pragma unroll 8
        for (int d = 0; d < 64; d++) {
            float a[8], bb[4];
            *(float4*)&a[0] = *(const float4*)(Qs + d * 132 + ty * 8);
            *(float4*)&a[4] = *(const float4*)(Qs + d * 132 + ty * 8 + 4);
            *(float4*)&bb[0] = *(const float4*)(Ks + d * 68 + tx * 4);
#pragma unroll
            for (int i = 0; i < 8; i++)
#pragma unroll
                for (int j = 0; j < 4; j++)
                    s[i][j] = fmaf(a[i], bb[j], s[i][j]);
        }

        // Scale + causal mask (only tiles touching the diagonal)
        const bool diag = (kt >= 2 * qt);
#pragma unroll
        for (int i = 0; i < 8; i++) {
            const int rg = qt * 128 + ty * 8 + i;
#pragma unroll
            for (int j = 0; j < 4; j++) {
                const int cg = kt * 64 + tx * 4 + j;
                float v = s[i][j] * 0.125f;
                if (diag && cg > rg) v = -CUDART_INF_F;
                s[i][j] = v;
            }
        }

        // Online softmax per row (reduce across the 16 tx lanes)
#pragma unroll
        for (int i = 0; i < 8; i++) {
            float tmax = fmaxf(fmaxf(s[i][0], s[i][1]), fmaxf(s[i][2], s[i][3]));
            tmax = fmaxf(tmax, __shfl_xor_sync(0xffffffffu, tmax, 1));
            tmax = fmaxf(tmax, __shfl_xor_sync(0xffffffffu, tmax, 2));
            tmax = fmaxf(tmax, __shfl_xor_sync(0xffffffffu, tmax, 4));
            tmax = fmaxf(tmax, __shfl_xor_sync(0xffffffffu, tmax, 8));
            const float mnew = fmaxf(m[i], tmax);
            const float corr = __expf(m[i] - mnew);
            m[i] = mnew;
            float ps = 0.f;
#pragma unroll
            for (int j = 0; j < 4; j++) {
                const float p = __expf(s[i][j] - mnew);
                s[i][j] = p;
                ps += p;
            }
            ps += __shfl_xor_sync(0xffffffffu, ps, 1);
            ps += __shfl_xor_sync(0xffffffffu, ps, 2);
            ps += __shfl_xor_sync(0xffffffffu, ps, 4);
            ps += __shfl_xor_sync(0xffffffffu, ps, 8);
            l[i] = l[i] * corr + ps;
#pragma unroll
            for (int j = 0; j < 4; j++) o[i][j] *= corr;
            // stage P
            float4 pv = {s[i][0], s[i][1], s[i][2], s[i][3]};
            *(float4*)(Ps + (ty * 8 + i) * 68 + tx * 4) = pv;
        }
        __syncthreads();

        // O += P @ V
#pragma unroll 4
        for (int k = 0; k < 64; k++) {
            float bb[4];
            *(float4*)&bb[0] = *(const float4*)(Vs + k * 68 + tx * 4);
#pragma unroll
            for (int i = 0; i < 8; i++) {
                const float a = Ps[(ty * 8 + i) * 68 + k];
#pragma unroll
                for (int j = 0; j < 4; j++)
                    o[i][j] = fmaf(a, bb[j], o[i][j]);
            }
        }
    }

    // Epilogue
#pragma unroll
    for (int i = 0; i < 8; i++) {
        const float inv = 1.f / l[i];
        float* op = g_attn + (size_t)(b * SS + qt * 128 + ty * 8 + i) * DD + h * 64 + tx * 4;
        float4 v = {o[i][0] * inv, o[i][1] * inv, o[i][2] * inv, o[i][3] * inv};
        *(float4*)op = v;
    }
}

// ---------------------------------------------------------------------------
extern "C" void kernel_launch(void* const* d_in, const int* in_sizes, int n_in,
                              void* d_out, int out_size)
{
    const float* x    = (const float*)d_in[0];  // [2,2048,1024]
    const float* wqkv = (const float*)d_in[1];  // [3072,1024]
    const float* wo   = (const float*)d_in[2];  // [1024,1024]
    float* out = (float*)d_out;                 // [2,2048,1024]

    float *pq = nullptr, *pa = nullptr;
    cudaGetSymbolAddress((void**)&pq, g_qkv);
    cudaGetSymbolAddress((void**)&pa, g_attn);

    // QKV = x @ wqkv^T : M=4096, N=3072, K=1024
    sgemm_nt<<<dim3(3072 / 128, 4096 / 128), 256>>>(x, wqkv, pq, 4096, 3072, 1024);

    // Attention
    const int attn_smem = (64 * 132 + 64 * 68 + 64 * 68 + 128 * 68) * 4;  // 103424 B
    cudaFuncSetAttribute(attn_kernel, cudaFuncAttributeMaxDynamicSharedMemorySize, attn_smem);
    attn_kernel<<<dim3(SS / 128, HH, BB), 256, attn_smem>>>();

    // out = attn @ wo^T : M=4096, N=1024, K=1024
    sgemm_nt<<<dim3(1024 / 128, 4096 / 128), 256>>>(pa, wo, out, 4096, 1024, 1024);
}

// round 4
// speedup vs baseline: 2.5445x; 1.0969x over previous
#include <cuda_runtime.h>
#include <cuda_bf16.h>
#include <math.h>
#include <math_constants.h>
#include <cstdint>

// Problem constants
#define BB 2
#define SS 2048
#define DD 1024
#define HH 16
#define DHH 64

// Scratch (no cudaMalloc allowed)
__device__ float g_qkv[(size_t)BB * SS * 3 * DD];   // [4096][3072]
__device__ float g_attn[(size_t)BB * SS * DD];      // [4096][1024]

// ============================ helpers ============================
__device__ __forceinline__ uint32_t smem_u32(const void* p) {
    uint32_t a;
    asm("{ .reg .u64 t; cvta.to.shared.u64 t, %1; cvt.u32.u64 %0, t; }" : "=r"(a) : "l"(p));
    return a;
}

// 64B-row swizzle: XOR 16B-chunk index (bits 4-5) with low row bits (bits 6-7)
#define SWZ64(o) ((o) ^ (((o) >> 2) & 0x30))

__device__ __forceinline__ void ldm_x4(uint32_t* r, uint32_t addr) {
    asm volatile("ldmatrix.sync.aligned.m8n8.x4.shared.b16 {%0,%1,%2,%3}, [%4];"
                 : "=r"(r[0]), "=r"(r[1]), "=r"(r[2]), "=r"(r[3]) : "r"(addr));
}

__device__ __forceinline__ void mma_bf16(float* d, const uint32_t* a, const uint32_t* b) {
    asm volatile(
        "mma.sync.aligned.m16n8k16.row.col.f32.bf16.bf16.f32 "
        "{%0,%1,%2,%3}, {%4,%5,%6,%7}, {%8,%9}, {%0,%1,%2,%3};"
        : "+f"(d[0]), "+f"(d[1]), "+f"(d[2]), "+f"(d[3])
        : "r"(a[0]), "r"(a[1]), "r"(a[2]), "r"(a[3]), "r"(b[0]), "r"(b[1]));
}

// split fp32x4 -> bf16 hi/lo packed pairs
__device__ __forceinline__ void split4(float4 v, uint2& hi, uint2& lo) {
    __nv_bfloat16 h0 = __float2bfloat16(v.x);
    __nv_bfloat16 h1 = __float2bfloat16(v.y);
    __nv_bfloat16 h2 = __float2bfloat16(v.z);
    __nv_bfloat16 h3 = __float2bfloat16(v.w);
    __nv_bfloat16 l0 = __float2bfloat16(v.x - __bfloat162float(h0));
    __nv_bfloat16 l1 = __float2bfloat16(v.y - __bfloat162float(h1));
    __nv_bfloat16 l2 = __float2bfloat16(v.z - __bfloat162float(h2));
    __nv_bfloat16 l3 = __float2bfloat16(v.w - __bfloat162float(h3));
    __nv_bfloat162 hp0 = __halves2bfloat162(h0, h1);
    __nv_bfloat162 hp1 = __halves2bfloat162(h2, h3);
    __nv_bfloat162 lp0 = __halves2bfloat162(l0, l1);
    __nv_bfloat162 lp1 = __halves2bfloat162(l2, l3);
    hi.x = *(uint32_t*)&hp0; hi.y = *(uint32_t*)&hp1;
    lo.x = *(uint32_t*)&lp0; lo.y = *(uint32_t*)&lp1;
}

// ---------------------------------------------------------------------------
// Split-bf16 mma.sync GEMM NT: C[m,n] = sum_k A[m,k] * B[n,k], K=1024 fixed.
// 128x128 CTA tile, BK=32, 256 threads = 8 warps (2m x 4n), warp tile 64x32.
// SMEM tiles in bf16 hi/lo pairs, 64B rows, swizzled for ldmatrix.
// ---------------------------------------------------------------------------
__global__ __launch_bounds__(256) void gemm_mma(const float* __restrict__ A,
                                                const float* __restrict__ B,
                                                float* __restrict__ C, int N)
{
    __shared__ __align__(1024) uint8_t smem[32768];  // Ah 8K | Al 8K | Bh 8K | Bl 8K

    const uint32_t sAh = smem_u32(smem);
    const uint32_t sAl = sAh + 8192;
    const uint32_t sBh = sAh + 16384;
    const uint32_t sBl = sAh + 24576;

    const int tid = threadIdx.x;
    const int lane = tid & 31;
    const int wid = tid >> 5;
    const int wm = wid & 1;      // 0..1 (m-dir)
    const int wn = wid >> 1;     // 0..3 (n-dir)
    const int bm = blockIdx.y * 128;
    const int bn = blockIdx.x * 128;

    const int lr = tid & 127;          // load row
    const int lc = (tid >> 7) * 16;    // load col base (fp32 elements)

    float acc[4][4][4] = {};

    const float* Aptr = A + (size_t)(bm + lr) * 1024 + lc;
    const float* Bptr = B + (size_t)(bn + lr) * 1024 + lc;

    float4 pa[4], pb[4];
#pragma unroll
    for (int f = 0; f < 4; f++) {
        pa[f] = *(const float4*)(Aptr + f * 4);
        pb[f] = *(const float4*)(Bptr + f * 4);
    }

    // Per-thread frag addresses (constant across chunks except kstep offset)
    const int a_row = wm * 64 + (lane & 15);
    const int a_kb = (lane >> 4) << 4;
    const int b_row = wn * 32 + (lane & 7) + ((lane >> 4) & 1) * 8;
    const int b_kb = ((lane >> 3) & 1) * 16;

    for (int kc = 0; kc < 32; kc++) {
        __syncthreads();
        // store current chunk to SMEM (fp32 -> bf16 hi/lo)
#pragma unroll
        for (int f = 0; f < 4; f++) {
            const uint32_t off = (uint32_t)lr * 64 + (uint32_t)(lc + f * 4) * 2;
            const uint32_t so = SWZ64(off);
            uint2 hi, lo;
            split4(pa[f], hi, lo);
            *(uint2*)(smem + so) = hi;
            *(uint2*)(smem + 8192 + so) = lo;
            split4(pb[f], hi, lo);
            *(uint2*)(smem + 16384 + so) = hi;
            *(uint2*)(smem + 24576 + so) = lo;
        }
        __syncthreads();

        // prefetch next chunk (overlaps with MMAs below)
        if (kc < 31) {
            Aptr += 32;
            Bptr += 32;
#pragma unroll
            for (int f = 0; f < 4; f++) {
                pa[f] = *(const float4*)(Aptr + f * 4);
                pb[f] = *(const float4*)(Bptr + f * 4);
            }
        }

        // compute: 2 k-steps of 16
#pragma unroll
        for (int ks = 0; ks < 2; ks++) {
            uint32_t ah[4][4], al[4][4], bh[4][2], bl[4][2];
#pragma unroll
            for (int mt = 0; mt < 4; mt++) {
                const uint32_t off = SWZ64((uint32_t)(a_row + mt * 16) * 64 + ks * 32 + a_kb);
                ldm_x4(ah[mt], sAh + off);
                ldm_x4(al[mt], sAl + off);
            }
#pragma unroll
            for (int nt2 = 0; nt2 < 2; nt2++) {
                const uint32_t off = SWZ64((uint32_t)(b_row + nt2 * 16) * 64 + ks * 32 + b_kb);
                uint32_t rh[4], rl[4];
                ldm_x4(rh, sBh + off);
                ldm_x4(rl, sBl + off);
                bh[nt2 * 2][0] = rh[0]; bh[nt2 * 2][1] = rh[1];
                bh[nt2 * 2 + 1][0] = rh[2]; bh[nt2 * 2 + 1][1] = rh[3];
                bl[nt2 * 2][0] = rl[0]; bl[nt2 * 2][1] = rl[1];
                bl[nt2 * 2 + 1][0] = rl[2]; bl[nt2 * 2 + 1][1] = rl[3];
            }
#pragma unroll
            for (int mt = 0; mt < 4; mt++)
#pragma unroll
                for (int nt = 0; nt < 4; nt++) {
                    mma_bf16(acc[mt][nt], ah[mt], bh[nt]);
                    mma_bf16(acc[mt][nt], ah[mt], bl[nt]);
                    mma_bf16(acc[mt][nt], al[mt], bh[nt]);
                }
        }
    }

    // Epilogue: fragment -> global (float2 stores)
#pragma unroll
    for (int mt = 0; mt < 4; mt++) {
        const int r0 = bm + wm * 64 + mt * 16 + (lane >> 2);
#pragma unroll
        for (int nt = 0; nt < 4; nt++) {
            const int c0 = bn + wn * 32 + nt * 8 + (lane & 3) * 2;
            float2 v0 = {acc[mt][nt][0], acc[mt][nt][1]};
            float2 v1 = {acc[mt][nt][2], acc[mt][nt][3]};
            *(float2*)(C + (size_t)r0 * N + c0) = v0;
            *(float2*)(C + (size_t)(r0 + 8) * N + c0) = v1;
        }
    }
}

// ---------------------------------------------------------------------------
// Register-tiled causal flash attention, fp32 (validated in R1/R2).
// ---------------------------------------------------------------------------
__global__ __launch_bounds__(256, 2) void attn_kernel()
{
    extern __shared__ float sm[];
    float* Qs = sm;               // [64 d][132]
    float* Ks = Qs + 64 * 132;    // [64 d][68]
    float* Vs = Ks + 64 * 68;     // [64 k][68]
    float* Ps = Vs + 64 * 68;     // [128 r][68]

    const int qt = (int)gridDim.x - 1 - (int)blockIdx.x;
    const int h = blockIdx.y;
    const int b = blockIdx.z;
    const int tid = threadIdx.x;
    const int ty = tid >> 4;
    const int tx = tid & 15;

    const float* base = g_qkv + (size_t)b * SS * 3072;

    {
        const int lr = tid >> 1;
        const int c0 = (tid & 1) * 32;
        const float* qp = base + (size_t)(qt * 128 + lr) * 3072 + h * 64 + c0;
#pragma unroll
        for (int f = 0; f < 8; f++) {
            float4 v = *(const float4*)(qp + f * 4);
            int d = c0 + f * 4;
            Qs[(d + 0) * 132 + lr] = v.x;
            Qs[(d + 1) * 132 + lr] = v.y;
            Qs[(d + 2) * 132 + lr] = v.z;
            Qs[(d + 3) * 132 + lr] = v.w;
        }
    }

    float m[8], l[8], o[8][4];
#pragma unroll
    for (int i = 0; i < 8; i++) {
        m[i] = -CUDART_INF_F;
        l[i] = 0.f;
#pragma unroll
        for (int j = 0; j < 4; j++) o[i][j] = 0.f;
    }

    const int kr = tid >> 2;
    const int kc0 = (tid & 3) * 16;
    const int nkt = 2 * qt + 2;

    for (int kt = 0; kt < nkt; kt++) {
        __syncthreads();
        {
            const float* kp = base + (size_t)(kt * 64 + kr) * 3072 + 1024 + h * 64 + kc0;
            const float* vp = kp + 1024;
#pragma unroll
            for (int f = 0; f < 4; f++) {
                float4 kv = *(const float4*)(kp + f * 4);
                int d = kc0 + f * 4;
                Ks[(d + 0) * 68 + kr] = kv.x;
                Ks[(d + 1) * 68 + kr] = kv.y;
                Ks[(d + 2) * 68 + kr] = kv.z;
                Ks[(d + 3) * 68 + kr] = kv.w;
                *(float4*)(Vs + kr * 68 + d) = *(const float4*)(vp + f * 4);
            }
        }
        __syncthreads();

        float s[8][4];
#pragma unroll
        for (int i = 0; i < 8; i++)
#pragma unroll
            for (int j = 0; j < 4; j++) s[i][j] = 0.f;

#pragma unroll 8
        for (int d = 0; d < 64; d++) {
            float a[8], bb[4];
            *(float4*)&a[0] = *(const float4*)(Qs + d * 132 + ty * 8);
            *(float4*)&a[4] = *(const float4*)(Qs + d * 132 + ty * 8 + 4);
            *(float4*)&bb[0] = *(const float4*)(Ks + d * 68 + tx * 4);
#pragma unroll
            for (int i = 0; i < 8; i++)
#pragma unroll
                for (int j = 0; j < 4; j++)
                    s[i][j] = fmaf(a[i], bb[j], s[i][j]);
        }

        const bool diag = (kt >= 2 * qt);
#pragma unroll
        for (int i = 0; i < 8; i++) {
            const int rg = qt * 128 + ty * 8 + i;
#pragma unroll
            for (int j = 0; j < 4; j++) {
                const int cg = kt * 64 + tx * 4 + j;
                float v = s[i][j] * 0.125f;
                if (diag && cg > rg) v = -CUDART_INF_F;
                s[i][j] = v;
            }
        }

#pragma unroll
        for (int i = 0; i < 8; i++) {
            float tmax = fmaxf(fmaxf(s[i][0], s[i][1]), fmaxf(s[i][2], s[i][3]));
            tmax = fmaxf(tmax, __shfl_xor_sync(0xffffffffu, tmax, 1));
            tmax = fmaxf(tmax, __shfl_xor_sync(0xffffffffu, tmax, 2));
            tmax = fmaxf(tmax, __shfl_xor_sync(0xffffffffu, tmax, 4));
            tmax = fmaxf(tmax, __shfl_xor_sync(0xffffffffu, tmax, 8));
            const float mnew = fmaxf(m[i], tmax);
            const float corr = __expf(m[i] - mnew);
            m[i] = mnew;
            float ps = 0.f;
#pragma unroll
            for (int j = 0; j < 4; j++) {
                const float p = __expf(s[i][j] - mnew);
                s[i][j] = p;
                ps += p;
            }
            ps += __shfl_xor_sync(0xffffffffu, ps, 1);
            ps += __shfl_xor_sync(0xffffffffu, ps, 2);
            ps += __shfl_xor_sync(0xffffffffu, ps, 4);
            ps += __shfl_xor_sync(0xffffffffu, ps, 8);
            l[i] = l[i] * corr + ps;
#pragma unroll
            for (int j = 0; j < 4; j++) o[i][j] *= corr;
            float4 pv = {s[i][0], s[i][1], s[i][2], s[i][3]};
            *(float4*)(Ps + (ty * 8 + i) * 68 + tx * 4) = pv;
        }
        __syncthreads();

#pragma unroll 4
        for (int k = 0; k < 64; k++) {
            float bb[4];
            *(float4*)&bb[0] = *(const float4*)(Vs + k * 68 + tx * 4);
#pragma unroll
            for (int i = 0; i < 8; i++) {
                const float a = Ps[(ty * 8 + i) * 68 + k];
#pragma unroll
                for (int j = 0; j < 4; j++)
                    o[i][j] = fmaf(a, bb[j], o[i][j]);
            }
        }
    }

#pragma unroll
    for (int i = 0; i < 8; i++) {
        const float inv = 1.f / l[i];
        float* op = g_attn + (size_t)(b * SS + qt * 128 + ty * 8 + i) * DD + h * 64 + tx * 4;
        float4 v = {o[i][0] * inv, o[i][1] * inv, o[i][2] * inv, o[i][3] * inv};
        *(float4*)op = v;
    }
}

// ---------------------------------------------------------------------------
extern "C" void kernel_launch(void* const* d_in, const int* in_sizes, int n_in,
                              void* d_out, int out_size)
{
    const float* x    = (const float*)d_in[0];  // [2,2048,1024]
    const float* wqkv = (const float*)d_in[1];  // [3072,1024]
    const float* wo   = (const float*)d_in[2];  // [1024,1024]
    float* out = (float*)d_out;                 // [2,2048,1024]

    float *pq = nullptr, *pa = nullptr;
    cudaGetSymbolAddress((void**)&pq, g_qkv);
    cudaGetSymbolAddress((void**)&pa, g_attn);

    // QKV = x @ wqkv^T : M=4096, N=3072, K=1024
    gemm_mma<<<dim3(3072 / 128, 4096 / 128), 256>>>(x, wqkv, pq, 3072);

    // Attention
    const int attn_smem = (64 * 132 + 64 * 68 + 64 * 68 + 128 * 68) * 4;  // 103424 B
    cudaFuncSetAttribute(attn_kernel, cudaFuncAttributeMaxDynamicSharedMemorySize, attn_smem);
    attn_kernel<<<dim3(SS / 128, HH, BB), 256, attn_smem>>>();

    // out = attn @ wo^T : M=4096, N=1024, K=1024
    gemm_mma<<<dim3(1024 / 128, 4096 / 128), 256>>>(pa, wo, out, 1024);
}

// round 5
// speedup vs baseline: 3.3902x; 1.3324x over previous
#include <cuda_runtime.h>
#include <cuda_bf16.h>
#include <math.h>
#include <math_constants.h>
#include <cstdint>

// Problem constants
#define BB 2
#define SS 2048
#define DD 1024
#define HH 16
#define DHH 64

// Scratch (no cudaMalloc allowed)
__device__ float g_qkv[(size_t)BB * SS * 3 * DD];   // [4096][3072] fp32
__device__ float g_attn[(size_t)BB * SS * DD];      // [4096][1024] fp32

// bf16 hi/lo split buffers
__device__ __align__(16) __nv_bfloat16 g_xh[4096 * 1024];
__device__ __align__(16) __nv_bfloat16 g_xl[4096 * 1024];
__device__ __align__(16) __nv_bfloat16 g_wh[3072 * 1024];
__device__ __align__(16) __nv_bfloat16 g_wl[3072 * 1024];
__device__ __align__(16) __nv_bfloat16 g_ah[4096 * 1024];
__device__ __align__(16) __nv_bfloat16 g_al[4096 * 1024];
__device__ __align__(16) __nv_bfloat16 g_woh[1024 * 1024];
__device__ __align__(16) __nv_bfloat16 g_wol[1024 * 1024];

// ============================ helpers ============================
__device__ __forceinline__ uint32_t smem_u32(const void* p) {
    uint32_t a;
    asm("{ .reg .u64 t; cvta.to.shared.u64 t, %1; cvt.u32.u64 %0, t; }" : "=r"(a) : "l"(p));
    return a;
}

__device__ __forceinline__ void ldm_x4(uint32_t* r, uint32_t addr) {
    asm volatile("ldmatrix.sync.aligned.m8n8.x4.shared.b16 {%0,%1,%2,%3}, [%4];"
                 : "=r"(r[0]), "=r"(r[1]), "=r"(r[2]), "=r"(r[3]) : "r"(addr));
}

__device__ __forceinline__ void mma_bf16(float* d, const uint32_t* a, const uint32_t* b) {
    asm volatile(
        "mma.sync.aligned.m16n8k16.row.col.f32.bf16.bf16.f32 "
        "{%0,%1,%2,%3}, {%4,%5,%6,%7}, {%8,%9}, {%0,%1,%2,%3};"
        : "+f"(d[0]), "+f"(d[1]), "+f"(d[2]), "+f"(d[3])
        : "r"(a[0]), "r"(a[1]), "r"(a[2]), "r"(a[3]), "r"(b[0]), "r"(b[1]));
}

__device__ __forceinline__ void cp16(uint32_t dst, const void* src) {
    asm volatile("cp.async.cg.shared.global [%0], [%1], 16;" :: "r"(dst), "l"(src));
}
#define CP_COMMIT() asm volatile("cp.async.commit_group;" ::: "memory")
#define CP_WAIT(n)  asm volatile("cp.async.wait_group %0;" :: "n"(n) : "memory")

// split fp32x4 -> bf16 hi/lo packed pairs
__device__ __forceinline__ void split4(float4 v, uint2& hi, uint2& lo) {
    __nv_bfloat16 h0 = __float2bfloat16(v.x);
    __nv_bfloat16 h1 = __float2bfloat16(v.y);
    __nv_bfloat16 h2 = __float2bfloat16(v.z);
    __nv_bfloat16 h3 = __float2bfloat16(v.w);
    __nv_bfloat16 l0 = __float2bfloat16(v.x - __bfloat162float(h0));
    __nv_bfloat16 l1 = __float2bfloat16(v.y - __bfloat162float(h1));
    __nv_bfloat16 l2 = __float2bfloat16(v.z - __bfloat162float(h2));
    __nv_bfloat16 l3 = __float2bfloat16(v.w - __bfloat162float(h3));
    __nv_bfloat162 hp0 = __halves2bfloat162(h0, h1);
    __nv_bfloat162 hp1 = __halves2bfloat162(h2, h3);
    __nv_bfloat162 lp0 = __halves2bfloat162(l0, l1);
    __nv_bfloat162 lp1 = __halves2bfloat162(l2, l3);
    hi.x = *(uint32_t*)&hp0; hi.y = *(uint32_t*)&hp1;
    lo.x = *(uint32_t*)&lp0; lo.y = *(uint32_t*)&lp1;
}

// Prepass: fp32 -> bf16 hi/lo
__global__ __launch_bounds__(256) void convert_split_k(const float4* __restrict__ src,
                                                       uint2* __restrict__ hi,
                                                       uint2* __restrict__ lo, int n4)
{
    for (int i = blockIdx.x * blockDim.x + threadIdx.x; i < n4; i += gridDim.x * blockDim.x) {
        uint2 h, l;
        split4(src[i], h, l);
        hi[i] = h;
        lo[i] = l;
    }
}

// Tile offset: two 64B k-rows packed per 128B SMEM line, SW128 swizzle.
// r = tile row 0..127, c = 16B chunk within row 0..3. Conflict-free for ldmatrix.
__device__ __forceinline__ uint32_t toff(int r, int c) {
    uint32_t o = ((uint32_t)(r >> 1) << 7) | ((uint32_t)(r & 1) << 6) | ((uint32_t)c << 4);
    return o ^ ((o >> 3) & 0x70);
}

// ---------------------------------------------------------------------------
// Split-bf16 mma.sync GEMM NT on pre-split inputs: C[m,n] = sum_k A[m,k]*B[n,k]
// K=1024. 128x128 CTA tile, BK=32, 256 threads = 8 warps (2m x 4n).
// cp.async double-buffered: buffer = Ah|Al|Bh|Bl 8KB each = 32KB, x2 = 64KB.
// ---------------------------------------------------------------------------
#define GSMEM 65536

__global__ __launch_bounds__(256) void gemm_bf16(const __nv_bfloat16* __restrict__ Ah,
                                                 const __nv_bfloat16* __restrict__ Al,
                                                 const __nv_bfloat16* __restrict__ Bh,
                                                 const __nv_bfloat16* __restrict__ Bl,
                                                 float* __restrict__ C, int N)
{
    extern __shared__ __align__(1024) uint8_t smem[];
    const uint32_t sb = smem_u32(smem);

    const int tid = threadIdx.x;
    const int lane = tid & 31;
    const int wid = tid >> 5;
    const int wm = wid & 1;
    const int wn = wid >> 1;
    const int bm = blockIdx.y * 128;
    const int bn = blockIdx.x * 128;

    // load indices: each thread does 2 16B chunks per tile
    const int idx0 = tid * 2;          // 0..510 even
    const int m0 = idx0 >> 2, c0 = idx0 & 3;
    const int m1 = (idx0 + 1) >> 2, c1 = (idx0 + 1) & 3;
    const uint32_t so0 = toff(m0, c0);
    const uint32_t so1 = toff(m1, c1);

    const __nv_bfloat16* pAh0 = Ah + (size_t)(bm + m0) * 1024 + c0 * 8;
    const __nv_bfloat16* pAh1 = Ah + (size_t)(bm + m1) * 1024 + c1 * 8;
    const __nv_bfloat16* pAl0 = Al + (size_t)(bm + m0) * 1024 + c0 * 8;
    const __nv_bfloat16* pAl1 = Al + (size_t)(bm + m1) * 1024 + c1 * 8;
    const __nv_bfloat16* pBh0 = Bh + (size_t)(bn + m0) * 1024 + c0 * 8;
    const __nv_bfloat16* pBh1 = Bh + (size_t)(bn + m1) * 1024 + c1 * 8;
    const __nv_bfloat16* pBl0 = Bl + (size_t)(bn + m0) * 1024 + c0 * 8;
    const __nv_bfloat16* pBl1 = Bl + (size_t)(bn + m1) * 1024 + c1 * 8;

    // fragment addresses
    const int a_row = wm * 64 + (lane & 15);
    const int a_k16 = lane >> 4;                       // chunk parity within kstep
    const int b_row = wn * 32 + (lane & 7) + ((lane >> 4) & 1) * 8;
    const int b_k16 = (lane >> 3) & 1;

    float acc[4][4][4] = {};

    // prologue: load chunk 0 into buf 0
    {
        cp16(sb + so0, pAh0);          cp16(sb + so1, pAh1);
        cp16(sb + 8192 + so0, pAl0);   cp16(sb + 8192 + so1, pAl1);
        cp16(sb + 16384 + so0, pBh0);  cp16(sb + 16384 + so1, pBh1);
        cp16(sb + 24576 + so0, pBl0);  cp16(sb + 24576 + so1, pBl1);
        CP_COMMIT();
    }

    for (int kc = 0; kc < 32; kc++) {
        const uint32_t buf = sb + (kc & 1) * 32768;
        if (kc < 31) {
            const uint32_t nbuf = sb + ((kc + 1) & 1) * 32768;
            const int ko = (kc + 1) * 32;
            cp16(nbuf + so0, pAh0 + ko);          cp16(nbuf + so1, pAh1 + ko);
            cp16(nbuf + 8192 + so0, pAl0 + ko);   cp16(nbuf + 8192 + so1, pAl1 + ko);
            cp16(nbuf + 16384 + so0, pBh0 + ko);  cp16(nbuf + 16384 + so1, pBh1 + ko);
            cp16(nbuf + 24576 + so0, pBl0 + ko);  cp16(nbuf + 24576 + so1, pBl1 + ko);
            CP_COMMIT();
            CP_WAIT(1);
        } else {
            CP_WAIT(0);
        }
        __syncthreads();

#pragma unroll
        for (int ks = 0; ks < 2; ks++) {
            uint32_t ah[4][4], al[4][4], bh[4][2], bl[4][2];
#pragma unroll
            for (int mt = 0; mt < 4; mt++) {
                const uint32_t off = toff(a_row + mt * 16, ks * 2 + a_k16);
                ldm_x4(ah[mt], buf + off);
                ldm_x4(al[mt], buf + 8192 + off);
            }
#pragma unroll
            for (int nt2 = 0; nt2 < 2; nt2++) {
                const uint32_t off = toff(b_row + nt2 * 16, ks * 2 + b_k16);
                uint32_t rh[4], rl[4];
                ldm_x4(rh, buf + 16384 + off);
                ldm_x4(rl, buf + 24576 + off);
                bh[nt2 * 2][0] = rh[0]; bh[nt2 * 2][1] = rh[1];
                bh[nt2 * 2 + 1][0] = rh[2]; bh[nt2 * 2 + 1][1] = rh[3];
                bl[nt2 * 2][0] = rl[0]; bl[nt2 * 2][1] = rl[1];
                bl[nt2 * 2 + 1][0] = rl[2]; bl[nt2 * 2 + 1][1] = rl[3];
            }
#pragma unroll
            for (int mt = 0; mt < 4; mt++)
#pragma unroll
                for (int nt = 0; nt < 4; nt++) {
                    mma_bf16(acc[mt][nt], ah[mt], bh[nt]);
                    mma_bf16(acc[mt][nt], ah[mt], bl[nt]);
                    mma_bf16(acc[mt][nt], al[mt], bh[nt]);
                }
        }
        __syncthreads();
    }

    // Epilogue
#pragma unroll
    for (int mt = 0; mt < 4; mt++) {
        const int r0 = bm + wm * 64 + mt * 16 + (lane >> 2);
#pragma unroll
        for (int nt = 0; nt < 4; nt++) {
            const int c = bn + wn * 32 + nt * 8 + (lane & 3) * 2;
            float2 v0 = {acc[mt][nt][0], acc[mt][nt][1]};
            float2 v1 = {acc[mt][nt][2], acc[mt][nt][3]};
            *(float2*)(C + (size_t)r0 * N + c) = v0;
            *(float2*)(C + (size_t)(r0 + 8) * N + c) = v1;
        }
    }
}

// ---------------------------------------------------------------------------
// Register-tiled causal flash attention, fp32 (validated).
// ---------------------------------------------------------------------------
__global__ __launch_bounds__(256, 2) void attn_kernel()
{
    extern __shared__ float sm[];
    float* Qs = sm;               // [64 d][132]
    float* Ks = Qs + 64 * 132;    // [64 d][68]
    float* Vs = Ks + 64 * 68;     // [64 k][68]
    float* Ps = Vs + 64 * 68;     // [128 r][68]

    const int qt = (int)gridDim.x - 1 - (int)blockIdx.x;
    const int h = blockIdx.y;
    const int b = blockIdx.z;
    const int tid = threadIdx.x;
    const int ty = tid >> 4;
    const int tx = tid & 15;

    const float* base = g_qkv + (size_t)b * SS * 3072;

    {
        const int lr = tid >> 1;
        const int c0 = (tid & 1) * 32;
        const float* qp = base + (size_t)(qt * 128 + lr) * 3072 + h * 64 + c0;
#pragma unroll
        for (int f = 0; f < 8; f++) {
            float4 v = *(const float4*)(qp + f * 4);
            int d = c0 + f * 4;
            Qs[(d + 0) * 132 + lr] = v.x;
            Qs[(d + 1) * 132 + lr] = v.y;
            Qs[(d + 2) * 132 + lr] = v.z;
            Qs[(d + 3) * 132 + lr] = v.w;
        }
    }

    float m[8], l[8], o[8][4];
#pragma unroll
    for (int i = 0; i < 8; i++) {
        m[i] = -CUDART_INF_F;
        l[i] = 0.f;
#pragma unroll
        for (int j = 0; j < 4; j++) o[i][j] = 0.f;
    }

    const int kr = tid >> 2;
    const int kc0 = (tid & 3) * 16;
    const int nkt = 2 * qt + 2;

    for (int kt = 0; kt < nkt; kt++) {
        __syncthreads();
        {
            const float* kp = base + (size_t)(kt * 64 + kr) * 3072 + 1024 + h * 64 + kc0;
            const float* vp = kp + 1024;
#pragma unroll
            for (int f = 0; f < 4; f++) {
                float4 kv = *(const float4*)(kp + f * 4);
                int d = kc0 + f * 4;
                Ks[(d + 0) * 68 + kr] = kv.x;
                Ks[(d + 1) * 68 + kr] = kv.y;
                Ks[(d + 2) * 68 + kr] = kv.z;
                Ks[(d + 3) * 68 + kr] = kv.w;
                *(float4*)(Vs + kr * 68 + d) = *(const float4*)(vp + f * 4);
            }
        }
        __syncthreads();

        float s[8][4];
#pragma unroll
        for (int i = 0; i < 8; i++)
#pragma unroll
            for (int j = 0; j < 4; j++) s[i][j] = 0.f;

#pragma unroll 8
        for (int d = 0; d < 64; d++) {
            float a[8], bb[4];
            *(float4*)&a[0] = *(const float4*)(Qs + d * 132 + ty * 8);
            *(float4*)&a[4] = *(const float4*)(Qs + d * 132 + ty * 8 + 4);
            *(float4*)&bb[0] = *(const float4*)(Ks + d * 68 + tx * 4);
#pragma unroll
            for (int i = 0; i < 8; i++)
#pragma unroll
                for (int j = 0; j < 4; j++)
                    s[i][j] = fmaf(a[i], bb[j], s[i][j]);
        }

        const bool diag = (kt >= 2 * qt);
#pragma unroll
        for (int i = 0; i < 8; i++) {
            const int rg = qt * 128 + ty * 8 + i;
#pragma unroll
            for (int j = 0; j < 4; j++) {
                const int cg = kt * 64 + tx * 4 + j;
                float v = s[i][j] * 0.125f;
                if (diag && cg > rg) v = -CUDART_INF_F;
                s[i][j] = v;
            }
        }

#pragma unroll
        for (int i = 0; i < 8; i++) {
            float tmax = fmaxf(fmaxf(s[i][0], s[i][1]), fmaxf(s[i][2], s[i][3]));
            tmax = fmaxf(tmax, __shfl_xor_sync(0xffffffffu, tmax, 1));
            tmax = fmaxf(tmax, __shfl_xor_sync(0xffffffffu, tmax, 2));
            tmax = fmaxf(tmax, __shfl_xor_sync(0xffffffffu, tmax, 4));
            tmax = fmaxf(tmax, __shfl_xor_sync(0xffffffffu, tmax, 8));
            const float mnew = fmaxf(m[i], tmax);
            const float corr = __expf(m[i] - mnew);
            m[i] = mnew;
            float ps = 0.f;
#pragma unroll
            for (int j = 0; j < 4; j++) {
                const float p = __expf(s[i][j] - mnew);
                s[i][j] = p;
                ps += p;
            }
            ps += __shfl_xor_sync(0xffffffffu, ps, 1);
            ps += __shfl_xor_sync(0xffffffffu, ps, 2);
            ps += __shfl_xor_sync(0xffffffffu, ps, 4);
            ps += __shfl_xor_sync(0xffffffffu, ps, 8);
            l[i] = l[i] * corr + ps;
#pragma unroll
            for (int j = 0; j < 4; j++) o[i][j] *= corr;
            float4 pv = {s[i][0], s[i][1], s[i][2], s[i][3]};
            *(float4*)(Ps + (ty * 8 + i) * 68 + tx * 4) = pv;
        }
        __syncthreads();

#pragma unroll 4
        for (int k = 0; k < 64; k++) {
            float bb[4];
            *(float4*)&bb[0] = *(const float4*)(Vs + k * 68 + tx * 4);
#pragma unroll
            for (int i = 0; i < 8; i++) {
                const float a = Ps[(ty * 8 + i) * 68 + k];
#pragma unroll
                for (int j = 0; j < 4; j++)
                    o[i][j] = fmaf(a, bb[j], o[i][j]);
            }
        }
    }

#pragma unroll
    for (int i = 0; i < 8; i++) {
        const float inv = 1.f / l[i];
        float* op = g_attn + (size_t)(b * SS + qt * 128 + ty * 8 + i) * DD + h * 64 + tx * 4;
        float4 v = {o[i][0] * inv, o[i][1] * inv, o[i][2] * inv, o[i][3] * inv};
        *(float4*)op = v;
    }
}

// ---------------------------------------------------------------------------
extern "C" void kernel_launch(void* const* d_in, const int* in_sizes, int n_in,
                              void* d_out, int out_size)
{
    const float* x    = (const float*)d_in[0];  // [2,2048,1024]
    const float* wqkv = (const float*)d_in[1];  // [3072,1024]
    const float* wo   = (const float*)d_in[2];  // [1024,1024]
    float* out = (float*)d_out;                 // [2,2048,1024]

    float *pq, *pa;
    __nv_bfloat16 *xh, *xl, *wh, *wl, *ah, *al, *woh, *wol;
    cudaGetSymbolAddress((void**)&pq, g_qkv);
    cudaGetSymbolAddress((void**)&pa, g_attn);
    cudaGetSymbolAddress((void**)&xh, g_xh);
    cudaGetSymbolAddress((void**)&xl, g_xl);
    cudaGetSymbolAddress((void**)&wh, g_wh);
    cudaGetSymbolAddress((void**)&wl, g_wl);
    cudaGetSymbolAddress((void**)&ah, g_ah);
    cudaGetSymbolAddress((void**)&al, g_al);
    cudaGetSymbolAddress((void**)&woh, g_woh);
    cudaGetSymbolAddress((void**)&wol, g_wol);

    cudaFuncSetAttribute(gemm_bf16, cudaFuncAttributeMaxDynamicSharedMemorySize, GSMEM);

    // Prepass conversions
    convert_split_k<<<512, 256>>>((const float4*)x, (uint2*)xh, (uint2*)xl, 4096 * 1024 / 4);
    convert_split_k<<<512, 256>>>((const float4*)wqkv, (uint2*)wh, (uint2*)wl, 3072 * 1024 / 4);
    convert_split_k<<<256, 256>>>((const float4*)wo, (uint2*)woh, (uint2*)wol, 1024 * 1024 / 4);

    // QKV = x @ wqkv^T
    gemm_bf16<<<dim3(3072 / 128, 4096 / 128), 256, GSMEM>>>(xh, xl, wh, wl, pq, 3072);

    // Attention
    const int attn_smem = (64 * 132 + 64 * 68 + 64 * 68 + 128 * 68) * 4;  // 103424 B
    cudaFuncSetAttribute(attn_kernel, cudaFuncAttributeMaxDynamicSharedMemorySize, attn_smem);
    attn_kernel<<<dim3(SS / 128, HH, BB), 256, attn_smem>>>();

    // Convert attention output, then out = attn @ wo^T
    convert_split_k<<<512, 256>>>((const float4*)pa, (uint2*)ah, (uint2*)al, 4096 * 1024 / 4);
    gemm_bf16<<<dim3(1024 / 128, 4096 / 128), 256, GSMEM>>>(ah, al, woh, wol, out, 1024);
}

// round 6
// speedup vs baseline: 6.9152x; 2.0398x over previous
#include <cuda_runtime.h>
#include <cuda_bf16.h>
#include <cuda_fp16.h>
#include <math.h>
#include <math_constants.h>
#include <cstdint>

// Problem constants
#define BB 2
#define SS 2048
#define DD 1024
#define HH 16
#define DHH 64

// log2(e)/8  (folded into Q so softmax is pure 2^x)
#define QSCALE 0.18033688011112042f

// ---------------- device scratch (no cudaMalloc allowed) ----------------
__device__ __align__(16) __nv_bfloat16 g_xh[4096 * 1024];
__device__ __align__(16) __nv_bfloat16 g_xl[4096 * 1024];
__device__ __align__(16) __nv_bfloat16 g_wh[3072 * 1024];
__device__ __align__(16) __nv_bfloat16 g_wl[3072 * 1024];
__device__ __align__(16) __nv_bfloat16 g_woh[1024 * 1024];
__device__ __align__(16) __nv_bfloat16 g_wol[1024 * 1024];

// Q,K (bf16 hi/lo) and V (fp16 hi/lo) in [b][h][s][d] layout
__device__ __align__(16) __nv_bfloat16 g_qh[BB * HH * SS * DHH];
__device__ __align__(16) __nv_bfloat16 g_ql[BB * HH * SS * DHH];
__device__ __align__(16) __nv_bfloat16 g_kh[BB * HH * SS * DHH];
__device__ __align__(16) __nv_bfloat16 g_kl[BB * HH * SS * DHH];
__device__ __align__(16) __half       g_vh[BB * HH * SS * DHH];
__device__ __align__(16) __half       g_vl[BB * HH * SS * DHH];

// attention output (bf16 hi/lo, token-major [4096][1024]) for proj GEMM
__device__ __align__(16) __nv_bfloat16 g_ah[4096 * 1024];
__device__ __align__(16) __nv_bfloat16 g_al[4096 * 1024];

// ============================ helpers ============================
__device__ __forceinline__ uint32_t smem_u32(const void* p) {
    uint32_t a;
    asm("{ .reg .u64 t; cvta.to.shared.u64 t, %1; cvt.u32.u64 %0, t; }" : "=r"(a) : "l"(p));
    return a;
}

__device__ __forceinline__ void ldm_x4(uint32_t* r, uint32_t addr) {
    asm volatile("ldmatrix.sync.aligned.m8n8.x4.shared.b16 {%0,%1,%2,%3}, [%4];"
                 : "=r"(r[0]), "=r"(r[1]), "=r"(r[2]), "=r"(r[3]) : "r"(addr));
}
__device__ __forceinline__ void ldm_x4_t(uint32_t* r, uint32_t addr) {
    asm volatile("ldmatrix.sync.aligned.m8n8.x4.trans.shared.b16 {%0,%1,%2,%3}, [%4];"
                 : "=r"(r[0]), "=r"(r[1]), "=r"(r[2]), "=r"(r[3]) : "r"(addr));
}

__device__ __forceinline__ void mma_bf16(float* d, const uint32_t* a, const uint32_t* b) {
    asm volatile(
        "mma.sync.aligned.m16n8k16.row.col.f32.bf16.bf16.f32 "
        "{%0,%1,%2,%3}, {%4,%5,%6,%7}, {%8,%9}, {%0,%1,%2,%3};"
        : "+f"(d[0]), "+f"(d[1]), "+f"(d[2]), "+f"(d[3])
        : "r"(a[0]), "r"(a[1]), "r"(a[2]), "r"(a[3]), "r"(b[0]), "r"(b[1]));
}
__device__ __forceinline__ void mma_f16(float* d, const uint32_t* a, const uint32_t* b) {
    asm volatile(
        "mma.sync.aligned.m16n8k16.row.col.f32.f16.f16.f32 "
        "{%0,%1,%2,%3}, {%4,%5,%6,%7}, {%8,%9}, {%0,%1,%2,%3};"
        : "+f"(d[0]), "+f"(d[1]), "+f"(d[2]), "+f"(d[3])
        : "r"(a[0]), "r"(a[1]), "r"(a[2]), "r"(a[3]), "r"(b[0]), "r"(b[1]));
}

__device__ __forceinline__ void cp16(uint32_t dst, const void* src) {
    asm volatile("cp.async.cg.shared.global [%0], [%1], 16;" :: "r"(dst), "l"(src));
}
#define CP_COMMIT() asm volatile("cp.async.commit_group;" ::: "memory")
#define CP_WAIT(n)  asm volatile("cp.async.wait_group %0;" :: "n"(n) : "memory")

__device__ __forceinline__ float ex2f(float x) {
    float y;
    asm("ex2.approx.ftz.f32 %0, %1;" : "=f"(y) : "f"(x));
    return y;
}
__device__ __forceinline__ uint32_t packh2(float a, float b) {
    __half2 h = __floats2half2_rn(a, b);
    return *(uint32_t*)&h;
}

// split fp32x4 -> bf16 hi/lo packed pairs
__device__ __forceinline__ void split4(float4 v, uint2& hi, uint2& lo) {
    __nv_bfloat16 h0 = __float2bfloat16(v.x);
    __nv_bfloat16 h1 = __float2bfloat16(v.y);
    __nv_bfloat16 h2 = __float2bfloat16(v.z);
    __nv_bfloat16 h3 = __float2bfloat16(v.w);
    __nv_bfloat16 l0 = __float2bfloat16(v.x - __bfloat162float(h0));
    __nv_bfloat16 l1 = __float2bfloat16(v.y - __bfloat162float(h1));
    __nv_bfloat16 l2 = __float2bfloat16(v.z - __bfloat162float(h2));
    __nv_bfloat16 l3 = __float2bfloat16(v.w - __bfloat162float(h3));
    __nv_bfloat162 hp0 = __halves2bfloat162(h0, h1);
    __nv_bfloat162 hp1 = __halves2bfloat162(h2, h3);
    __nv_bfloat162 lp0 = __halves2bfloat162(l0, l1);
    __nv_bfloat162 lp1 = __halves2bfloat162(l2, l3);
    hi.x = *(uint32_t*)&hp0; hi.y = *(uint32_t*)&hp1;
    lo.x = *(uint32_t*)&lp0; lo.y = *(uint32_t*)&lp1;
}

__device__ __forceinline__ void store_split_bf16(__nv_bfloat16* H, __nv_bfloat16* L,
                                                 size_t idx, float v0, float v1) {
    __nv_bfloat16 h0 = __float2bfloat16(v0), h1 = __float2bfloat16(v1);
    __nv_bfloat16 l0 = __float2bfloat16(v0 - __bfloat162float(h0));
    __nv_bfloat16 l1 = __float2bfloat16(v1 - __bfloat162float(h1));
    *(__nv_bfloat162*)(H + idx) = __halves2bfloat162(h0, h1);
    *(__nv_bfloat162*)(L + idx) = __halves2bfloat162(l0, l1);
}
__device__ __forceinline__ void store_split_f16(__half* H, __half* L,
                                                size_t idx, float v0, float v1) {
    __half h0 = __float2half(v0), h1 = __float2half(v1);
    __half l0 = __float2half(v0 - __half2float(h0));
    __half l1 = __float2half(v1 - __half2float(h1));
    *(__half2*)(H + idx) = __halves2half2(h0, h1);
    *(__half2*)(L + idx) = __halves2half2(l0, l1);
}

// Prepass: fp32 -> bf16 hi/lo
__global__ __launch_bounds__(256) void convert_split_k(const float4* __restrict__ src,
                                                       uint2* __restrict__ hi,
                                                       uint2* __restrict__ lo, int n4)
{
    for (int i = blockIdx.x * blockDim.x + threadIdx.x; i < n4; i += gridDim.x * blockDim.x) {
        uint2 h, l;
        split4(src[i], h, l);
        hi[i] = h;
        lo[i] = l;
    }
}

// Tile offset: two 64B k-rows packed per 128B SMEM line, SW128 swizzle (GEMM tiles).
__device__ __forceinline__ uint32_t toff(int r, int c) {
    uint32_t o = ((uint32_t)(r >> 1) << 7) | ((uint32_t)(r & 1) << 6) | ((uint32_t)c << 4);
    return o ^ ((o >> 3) & 0x70);
}
// 128B-row SW128 swizzle (attention tiles)
__device__ __forceinline__ uint32_t soff(int r, int c) {
    uint32_t o = (uint32_t)r * 128 + (uint32_t)c * 16;
    return o ^ ((o >> 3) & 0x70);
}

// ---------------------------------------------------------------------------
// Split-bf16 mma.sync GEMM NT: C[m,n] = sum_k A[m,k]*B[n,k], K=1024.
// MODE 0: plain fp32 C.  MODE 1: QKV scatter epilogue (Q scaled, bf16/fp16 splits).
// ---------------------------------------------------------------------------
#define GSMEM 65536

template <int MODE>
__global__ __launch_bounds__(256) void gemm_bf16(const __nv_bfloat16* __restrict__ Ah,
                                                 const __nv_bfloat16* __restrict__ Al,
                                                 const __nv_bfloat16* __restrict__ Bh,
                                                 const __nv_bfloat16* __restrict__ Bl,
                                                 float* __restrict__ C, int N)
{
    extern __shared__ __align__(1024) uint8_t smem[];
    const uint32_t sb = smem_u32(smem);

    const int tid = threadIdx.x;
    const int lane = tid & 31;
    const int wid = tid >> 5;
    const int wm = wid & 1;
    const int wn = wid >> 1;
    const int bm = blockIdx.y * 128;
    const int bn = blockIdx.x * 128;

    const int idx0 = tid * 2;
    const int m0 = idx0 >> 2, c0 = idx0 & 3;
    const int m1 = (idx0 + 1) >> 2, c1 = (idx0 + 1) & 3;
    const uint32_t so0 = toff(m0, c0);
    const uint32_t so1 = toff(m1, c1);

    const __nv_bfloat16* pAh0 = Ah + (size_t)(bm + m0) * 1024 + c0 * 8;
    const __nv_bfloat16* pAh1 = Ah + (size_t)(bm + m1) * 1024 + c1 * 8;
    const __nv_bfloat16* pAl0 = Al + (size_t)(bm + m0) * 1024 + c0 * 8;
    const __nv_bfloat16* pAl1 = Al + (size_t)(bm + m1) * 1024 + c1 * 8;
    const __nv_bfloat16* pBh0 = Bh + (size_t)(bn + m0) * 1024 + c0 * 8;
    const __nv_bfloat16* pBh1 = Bh + (size_t)(bn + m1) * 1024 + c1 * 8;
    const __nv_bfloat16* pBl0 = Bl + (size_t)(bn + m0) * 1024 + c0 * 8;
    const __nv_bfloat16* pBl1 = Bl + (size_t)(bn + m1) * 1024 + c1 * 8;

    const int a_row = wm * 64 + (lane & 15);
    const int a_k16 = lane >> 4;
    const int b_row = wn * 32 + (lane & 7) + ((lane >> 4) & 1) * 8;
    const int b_k16 = (lane >> 3) & 1;

    float acc[4][4][4] = {};

    {
        cp16(sb + so0, pAh0);          cp16(sb + so1, pAh1);
        cp16(sb + 8192 + so0, pAl0);   cp16(sb + 8192 + so1, pAl1);
        cp16(sb + 16384 + so0, pBh0);  cp16(sb + 16384 + so1, pBh1);
        cp16(sb + 24576 + so0, pBl0);  cp16(sb + 24576 + so1, pBl1);
        CP_COMMIT();
    }

    for (int kc = 0; kc < 32; kc++) {
        const uint32_t buf = sb + (kc & 1) * 32768;
        if (kc < 31) {
            const uint32_t nbuf = sb + ((kc + 1) & 1) * 32768;
            const int ko = (kc + 1) * 32;
            cp16(nbuf + so0, pAh0 + ko);          cp16(nbuf + so1, pAh1 + ko);
            cp16(nbuf + 8192 + so0, pAl0 + ko);   cp16(nbuf + 8192 + so1, pAl1 + ko);
            cp16(nbuf + 16384 + so0, pBh0 + ko);  cp16(nbuf + 16384 + so1, pBh1 + ko);
            cp16(nbuf + 24576 + so0, pBl0 + ko);  cp16(nbuf + 24576 + so1, pBl1 + ko);
            CP_COMMIT();
            CP_WAIT(1);
        } else {
            CP_WAIT(0);
        }
        __syncthreads();

#pragma unroll
        for (int ks = 0; ks < 2; ks++) {
            uint32_t ah[4][4], al[4][4], bh[4][2], bl[4][2];
#pragma unroll
            for (int mt = 0; mt < 4; mt++) {
                const uint32_t off = toff(a_row + mt * 16, ks * 2 + a_k16);
                ldm_x4(ah[mt], buf + off);
                ldm_x4(al[mt], buf + 8192 + off);
            }
#pragma unroll
            for (int nt2 = 0; nt2 < 2; nt2++) {
                const uint32_t off = toff(b_row + nt2 * 16, ks * 2 + b_k16);
                uint32_t rh[4], rl[4];
                ldm_x4(rh, buf + 16384 + off);
                ldm_x4(rl, buf + 24576 + off);
                bh[nt2 * 2][0] = rh[0]; bh[nt2 * 2][1] = rh[1];
                bh[nt2 * 2 + 1][0] = rh[2]; bh[nt2 * 2 + 1][1] = rh[3];
                bl[nt2 * 2][0] = rl[0]; bl[nt2 * 2][1] = rl[1];
                bl[nt2 * 2 + 1][0] = rl[2]; bl[nt2 * 2 + 1][1] = rl[3];
            }
#pragma unroll
            for (int mt = 0; mt < 4; mt++)
#pragma unroll
                for (int nt = 0; nt < 4; nt++) {
                    mma_bf16(acc[mt][nt], ah[mt], bh[nt]);
                    mma_bf16(acc[mt][nt], ah[mt], bl[nt]);
                    mma_bf16(acc[mt][nt], al[mt], bh[nt]);
                }
        }
        __syncthreads();
    }

    if (MODE == 0) {
#pragma unroll
        for (int mt = 0; mt < 4; mt++) {
            const int r0 = bm + wm * 64 + mt * 16 + (lane >> 2);
#pragma unroll
            for (int nt = 0; nt < 4; nt++) {
                const int c = bn + wn * 32 + nt * 8 + (lane & 3) * 2;
                float2 v0 = {acc[mt][nt][0], acc[mt][nt][1]};
                float2 v1 = {acc[mt][nt][2], acc[mt][nt][3]};
                *(float2*)(C + (size_t)r0 * N + c) = v0;
                *(float2*)(C + (size_t)(r0 + 8) * N + c) = v1;
            }
        }
    } else {
        // QKV scatter: row=token, col in [0,3072)
#pragma unroll
        for (int mt = 0; mt < 4; mt++) {
            const int row = bm + wm * 64 + mt * 16 + (lane >> 2);
#pragma unroll
            for (int nt = 0; nt < 4; nt++) {
                const int c = bn + wn * 32 + nt * 8 + (lane & 3) * 2;
                const int which = c >> 10;
                const int hh = (c >> 6) & 15;
                const int d = c & 63;
#pragma unroll
                for (int half = 0; half < 2; half++) {
                    const int r = row + half * 8;
                    const int bb = r >> 11;
                    const int s = r & 2047;
                    const size_t idx = (((size_t)(bb * 16 + hh)) * SS + s) * 64 + d;
                    float v0 = acc[mt][nt][half * 2];
                    float v1 = acc[mt][nt][half * 2 + 1];
                    if (which == 0) {
                        store_split_bf16(g_qh, g_ql, idx, v0 * QSCALE, v1 * QSCALE);
                    } else if (which == 1) {
                        store_split_bf16(g_kh, g_kl, idx, v0, v1);
                    } else {
                        store_split_f16(g_vh, g_vl, idx, v0, v1);
                    }
                }
            }
        }
    }
}

// ---------------------------------------------------------------------------
// Flash attention on mma.sync.
// CTA = (qt, h, b). 256 threads, 8 warps, each warp owns 16 q-rows.
// S = Q*K^T in 3-term split-bf16 (scale folded into Q, log2 domain).
// Softmax in registers; P (fp16) feeds PV MMA directly from registers.
// PV: P * (Vh + Vl) fp16, plus ones-column MMA for row sums l.
// SMEM: Qh 16K | Ql 16K | K bufs 2x(8K+8K) | V bufs 2x(8K+8K) = 96KB.
// ---------------------------------------------------------------------------
#define ASMEM 98304

__device__ __forceinline__ void attn_load_kv(uint32_t sb, size_t bh, int kt, int buf, int tid)
{
#pragma unroll
    for (int i = 0; i < 8; i++) {
        const int id = tid + 256 * i;
        const int t = id >> 9;        // 0 Kh,1 Kl,2 Vh,3 Vl
        const int w = id & 511;
        const int r = w >> 3, c = w & 7;
        const uint32_t swz = soff(r, c);
        const size_t gidx = (bh * SS + (size_t)kt * 64 + r) * 64 + c * 8;
        uint32_t dst;
        const void* src;
        if (t == 0)      { dst = sb + 32768 + buf * 16384 + swz;        src = g_kh + gidx; }
        else if (t == 1) { dst = sb + 32768 + buf * 16384 + 8192 + swz; src = g_kl + gidx; }
        else if (t == 2) { dst = sb + 65536 + buf * 16384 + swz;        src = g_vh + gidx; }
        else             { dst = sb + 65536 + buf * 16384 + 8192 + swz; src = g_vl + gidx; }
        cp16(dst, src);
    }
}

__global__ __launch_bounds__(256) void attn_mma()
{
    extern __shared__ __align__(1024) uint8_t sm[];
    const uint32_t sb = smem_u32(sm);
    const int qt = (int)gridDim.x - 1 - (int)blockIdx.x;  // heavy tiles first
    const int h = blockIdx.y;
    const int b = blockIdx.z;
    const int tid = threadIdx.x;
    const int lane = tid & 31;
    const int wid = tid >> 5;
    const size_t bh = (size_t)(b * HH + h);
    const int nkt = 2 * qt + 2;

    // prologue: load Q (hi/lo) + KV(0) as group 0, KV(1) as group 1
#pragma unroll
    for (int i = 0; i < 8; i++) {
        const int id = tid + 256 * i;
        const int t = id >> 10;       // 0 Qh, 1 Ql
        const int w = id & 1023;
        const int r = w >> 3, c = w & 7;
        const uint32_t dst = sb + t * 16384 + soff(r, c);
        const size_t gidx = (bh * SS + (size_t)qt * 128 + r) * 64 + c * 8;
        cp16(dst, t == 0 ? (const void*)(g_qh + gidx) : (const void*)(g_ql + gidx));
    }
    attn_load_kv(sb, bh, 0, 0, tid);
    CP_COMMIT();
    attn_load_kv(sb, bh, 1, 1, tid);
    CP_COMMIT();

    float m1 = -CUDART_INF_F, m2 = -CUDART_INF_F;
    float o[8][4] = {};
    float lac[4] = {};
    const uint32_t ones2[2] = {0x3C003C00u, 0x3C003C00u};

    const int rg1 = qt * 128 + wid * 16 + (lane >> 2);  // global q row (half 1)

    for (int kt = 0; kt < nkt; kt++) {
        CP_WAIT(1);
        __syncthreads();

        const uint32_t kb = sb + 32768 + (kt & 1) * 16384;
        const uint32_t vb = sb + 65536 + (kt & 1) * 16384;

        const bool skipall = (kt == 2 * qt + 1) && (wid < 4);
        if (!skipall) {
            // ---- S = Q @ K^T (3-term split bf16) ----
            float s[8][4];
#pragma unroll
            for (int nt = 0; nt < 8; nt++)
#pragma unroll
                for (int j = 0; j < 4; j++) s[nt][j] = 0.f;

#pragma unroll
            for (int ks = 0; ks < 4; ks++) {
                uint32_t qa[4], ql[4];
                const uint32_t offA = soff(wid * 16 + (lane & 15), ks * 2 + (lane >> 4));
                ldm_x4(qa, sb + offA);
                ldm_x4(ql, sb + 16384 + offA);
#pragma unroll
                for (int nb = 0; nb < 4; nb++) {
                    const uint32_t offB = soff(nb * 16 + (lane & 7) + ((lane >> 4) & 1) * 8,
                                               ks * 2 + ((lane >> 3) & 1));
                    uint32_t rh[4], rl[4];
                    ldm_x4(rh, kb + offB);
                    ldm_x4(rl, kb + 8192 + offB);
                    mma_bf16(s[nb * 2], qa, rh);
                    mma_bf16(s[nb * 2], qa, rl);
                    mma_bf16(s[nb * 2], ql, rh);
                    mma_bf16(s[nb * 2 + 1], qa, rh + 2);
                    mma_bf16(s[nb * 2 + 1], qa, rl + 2);
                    mma_bf16(s[nb * 2 + 1], ql, rh + 2);
                }
            }

            // ---- causal mask (diag tiles only) ----
            const bool domask = (kt == 2 * qt && wid < 4) || (kt == 2 * qt + 1 && wid >= 4);
            if (domask) {
#pragma unroll
                for (int nt = 0; nt < 8; nt++) {
                    const int cg = kt * 64 + nt * 8 + (lane & 3) * 2;
#pragma unroll
                    for (int j = 0; j < 4; j++) {
                        const int col = cg + (j & 1);
                        const int row = rg1 + ((j >> 1) << 3);
                        if (col > row) s[nt][j] = -1e30f;
                    }
                }
            }

            // ---- online softmax (log2 domain) ----
            float t1 = -CUDART_INF_F, t2 = -CUDART_INF_F;
#pragma unroll
            for (int nt = 0; nt < 8; nt++) {
                t1 = fmaxf(t1, fmaxf(s[nt][0], s[nt][1]));
                t2 = fmaxf(t2, fmaxf(s[nt][2], s[nt][3]));
            }
            t1 = fmaxf(t1, __shfl_xor_sync(0xffffffffu, t1, 1));
            t1 = fmaxf(t1, __shfl_xor_sync(0xffffffffu, t1, 2));
            t2 = fmaxf(t2, __shfl_xor_sync(0xffffffffu, t2, 1));
            t2 = fmaxf(t2, __shfl_xor_sync(0xffffffffu, t2, 2));
            const float mn1 = fmaxf(m1, t1);
            const float mn2 = fmaxf(m2, t2);
            const float cr1 = ex2f(m1 - mn1);
            const float cr2 = ex2f(m2 - mn2);
            m1 = mn1; m2 = mn2;

            uint32_t p1[8], p2[8];
#pragma unroll
            for (int nt = 0; nt < 8; nt++) {
                p1[nt] = packh2(ex2f(s[nt][0] - mn1), ex2f(s[nt][1] - mn1));
                p2[nt] = packh2(ex2f(s[nt][2] - mn2), ex2f(s[nt][3] - mn2));
            }
#pragma unroll
            for (int nt = 0; nt < 8; nt++) {
                o[nt][0] *= cr1; o[nt][1] *= cr1;
                o[nt][2] *= cr2; o[nt][3] *= cr2;
            }
            lac[0] *= cr1; lac[1] *= cr1; lac[2] *= cr2; lac[3] *= cr2;

            // ---- O += P @ (Vh + Vl), l += P @ 1 ----
#pragma unroll
            for (int ks = 0; ks < 4; ks++) {
                uint32_t A[4] = {p1[ks * 2], p2[ks * 2], p1[ks * 2 + 1], p2[ks * 2 + 1]};
#pragma unroll
                for (int nb = 0; nb < 4; nb++) {
                    const uint32_t offV = soff(ks * 16 + (lane & 15), nb * 2 + (lane >> 4));
                    uint32_t vh[4], vl[4];
                    ldm_x4_t(vh, vb + offV);
                    ldm_x4_t(vl, vb + 8192 + offV);
                    mma_f16(o[nb * 2], A, vh);
                    mma_f16(o[nb * 2], A, vl);
                    mma_f16(o[nb * 2 + 1], A, vh + 2);
                    mma_f16(o[nb * 2 + 1], A, vl + 2);
                }
                mma_f16(lac, A, ones2);
            }
        }

        __syncthreads();
        if (kt + 2 < nkt) attn_load_kv(sb, bh, kt + 2, kt & 1, tid);
        CP_COMMIT();
    }

    // ---- epilogue: normalize, split to bf16 hi/lo, write [token][1024] ----
    const float inv1 = 1.f / lac[0];
    const float inv2 = 1.f / lac[2];
    const size_t tok1 = (size_t)(b * SS + qt * 128 + wid * 16 + (lane >> 2));
#pragma unroll
    for (int nt = 0; nt < 8; nt++) {
        const int col = h * 64 + nt * 8 + (lane & 3) * 2;
        store_split_bf16(g_ah, g_al, tok1 * 1024 + col, o[nt][0] * inv1, o[nt][1] * inv1);
        store_split_bf16(g_ah, g_al, (tok1 + 8) * 1024 + col, o[nt][2] * inv2, o[nt][3] * inv2);
    }
}

// ---------------------------------------------------------------------------
extern "C" void kernel_launch(void* const* d_in, const int* in_sizes, int n_in,
                              void* d_out, int out_size)
{
    const float* x    = (const float*)d_in[0];  // [2,2048,1024]
    const float* wqkv = (const float*)d_in[1];  // [3072,1024]
    const float* wo   = (const float*)d_in[2];  // [1024,1024]
    float* out = (float*)d_out;                 // [2,2048,1024]

    __nv_bfloat16 *xh, *xl, *wh, *wl, *woh, *wol, *ah, *al;
    cudaGetSymbolAddress((void**)&xh, g_xh);
    cudaGetSymbolAddress((void**)&xl, g_xl);
    cudaGetSymbolAddress((void**)&wh, g_wh);
    cudaGetSymbolAddress((void**)&wl, g_wl);
    cudaGetSymbolAddress((void**)&woh, g_woh);
    cudaGetSymbolAddress((void**)&wol, g_wol);
    cudaGetSymbolAddress((void**)&ah, g_ah);
    cudaGetSymbolAddress((void**)&al, g_al);

    cudaFuncSetAttribute(gemm_bf16<0>, cudaFuncAttributeMaxDynamicSharedMemorySize, GSMEM);
    cudaFuncSetAttribute(gemm_bf16<1>, cudaFuncAttributeMaxDynamicSharedMemorySize, GSMEM);
    cudaFuncSetAttribute(attn_mma, cudaFuncAttributeMaxDynamicSharedMemorySize, ASMEM);

    // Prepass conversions
    convert_split_k<<<512, 256>>>((const float4*)x, (uint2*)xh, (uint2*)xl, 4096 * 1024 / 4);
    convert_split_k<<<512, 256>>>((const float4*)wqkv, (uint2*)wh, (uint2*)wl, 3072 * 1024 / 4);
    convert_split_k<<<256, 256>>>((const float4*)wo, (uint2*)woh, (uint2*)wol, 1024 * 1024 / 4);

    // QKV = x @ wqkv^T with scatter epilogue -> g_qh/ql/kh/kl/vh/vl
    gemm_bf16<1><<<dim3(3072 / 128, 4096 / 128), 256, GSMEM>>>(xh, xl, wh, wl, nullptr, 3072);

    // Attention -> g_ah/g_al
    attn_mma<<<dim3(SS / 128, HH, BB), 256, ASMEM>>>();

    // out = attn @ wo^T
    gemm_bf16<0><<<dim3(1024 / 128, 4096 / 128), 256, GSMEM>>>(ah, al, woh, wol, out, 1024);
}

// round 7
// speedup vs baseline: 8.2970x; 1.1998x over previous
#include <cuda_runtime.h>
#include <cuda_bf16.h>
#include <cuda_fp16.h>
#include <math.h>
#include <math_constants.h>
#include <cstdint>

// Problem constants
#define BB 2
#define SS 2048
#define DD 1024
#define HH 16
#define DHH 64

// log2(e)/8  (folded into Q so softmax is pure 2^x)
#define QSCALE 0.18033688011112042f
#define WSC 256.0f
#define WSCI (1.0f / 256.0f)

// ---------------- device scratch (no cudaMalloc allowed) ----------------
__device__ __align__(16) __half g_xf[4096 * 1024];          // x, fp16
__device__ __align__(16) __half g_wh[3072 * 1024];          // wqkv*256 hi
__device__ __align__(16) __half g_wl[3072 * 1024];          // wqkv*256 lo
__device__ __align__(16) __half g_woh[1024 * 1024];         // wo*256 hi
__device__ __align__(16) __half g_wol[1024 * 1024];         // wo*256 lo
__device__ __align__(16) __half g_af[4096 * 1024];          // attn out, fp16

// Q,K (bf16 hi/lo) and V (fp16 hi/lo) in [b][h][s][d] layout
__device__ __align__(16) __nv_bfloat16 g_qh[BB * HH * SS * DHH];
__device__ __align__(16) __nv_bfloat16 g_ql[BB * HH * SS * DHH];
__device__ __align__(16) __nv_bfloat16 g_kh[BB * HH * SS * DHH];
__device__ __align__(16) __nv_bfloat16 g_kl[BB * HH * SS * DHH];
__device__ __align__(16) __half       g_vh[BB * HH * SS * DHH];
__device__ __align__(16) __half       g_vl[BB * HH * SS * DHH];

// ============================ helpers ============================
__device__ __forceinline__ uint32_t smem_u32(const void* p) {
    uint32_t a;
    asm("{ .reg .u64 t; cvta.to.shared.u64 t, %1; cvt.u32.u64 %0, t; }" : "=r"(a) : "l"(p));
    return a;
}

__device__ __forceinline__ void ldm_x4(uint32_t* r, uint32_t addr) {
    asm volatile("ldmatrix.sync.aligned.m8n8.x4.shared.b16 {%0,%1,%2,%3}, [%4];"
                 : "=r"(r[0]), "=r"(r[1]), "=r"(r[2]), "=r"(r[3]) : "r"(addr));
}
__device__ __forceinline__ void ldm_x4_t(uint32_t* r, uint32_t addr) {
    asm volatile("ldmatrix.sync.aligned.m8n8.x4.trans.shared.b16 {%0,%1,%2,%3}, [%4];"
                 : "=r"(r[0]), "=r"(r[1]), "=r"(r[2]), "=r"(r[3]) : "r"(addr));
}

__device__ __forceinline__ void mma_bf16(float* d, const uint32_t* a, const uint32_t* b) {
    asm volatile(
        "mma.sync.aligned.m16n8k16.row.col.f32.bf16.bf16.f32 "
        "{%0,%1,%2,%3}, {%4,%5,%6,%7}, {%8,%9}, {%0,%1,%2,%3};"
        : "+f"(d[0]), "+f"(d[1]), "+f"(d[2]), "+f"(d[3])
        : "r"(a[0]), "r"(a[1]), "r"(a[2]), "r"(a[3]), "r"(b[0]), "r"(b[1]));
}
__device__ __forceinline__ void mma_f16(float* d, const uint32_t* a, const uint32_t* b) {
    asm volatile(
        "mma.sync.aligned.m16n8k16.row.col.f32.f16.f16.f32 "
        "{%0,%1,%2,%3}, {%4,%5,%6,%7}, {%8,%9}, {%0,%1,%2,%3};"
        : "+f"(d[0]), "+f"(d[1]), "+f"(d[2]), "+f"(d[3])
        : "r"(a[0]), "r"(a[1]), "r"(a[2]), "r"(a[3]), "r"(b[0]), "r"(b[1]));
}

__device__ __forceinline__ void cp16(uint32_t dst, const void* src) {
    asm volatile("cp.async.cg.shared.global [%0], [%1], 16;" :: "r"(dst), "l"(src));
}
#define CP_COMMIT() asm volatile("cp.async.commit_group;" ::: "memory")
#define CP_WAIT(n)  asm volatile("cp.async.wait_group %0;" :: "n"(n) : "memory")

__device__ __forceinline__ float ex2f(float x) {
    float y;
    asm("ex2.approx.ftz.f32 %0, %1;" : "=f"(y) : "f"(x));
    return y;
}
__device__ __forceinline__ uint32_t packh2(float a, float b) {
    __half2 h = __floats2half2_rn(a, b);
    return *(uint32_t*)&h;
}

__device__ __forceinline__ void store_split_bf16(__nv_bfloat16* H, __nv_bfloat16* L,
                                                 size_t idx, float v0, float v1) {
    __nv_bfloat16 h0 = __float2bfloat16(v0), h1 = __float2bfloat16(v1);
    __nv_bfloat16 l0 = __float2bfloat16(v0 - __bfloat162float(h0));
    __nv_bfloat16 l1 = __float2bfloat16(v1 - __bfloat162float(h1));
    *(__nv_bfloat162*)(H + idx) = __halves2bfloat162(h0, h1);
    *(__nv_bfloat162*)(L + idx) = __halves2bfloat162(l0, l1);
}
__device__ __forceinline__ void store_split_f16(__half* H, __half* L,
                                                size_t idx, float v0, float v1) {
    __half h0 = __float2half(v0), h1 = __float2half(v1);
    __half l0 = __float2half(v0 - __half2float(h0));
    __half l1 = __float2half(v1 - __half2float(h1));
    *(__half2*)(H + idx) = __halves2half2(h0, h1);
    *(__half2*)(L + idx) = __halves2half2(l0, l1);
}

// Prepass: fp32 -> fp16 (single)
__global__ __launch_bounds__(256) void convert_f16(const float4* __restrict__ src,
                                                   uint2* __restrict__ dst, int n4)
{
    for (int i = blockIdx.x * blockDim.x + threadIdx.x; i < n4; i += gridDim.x * blockDim.x) {
        float4 v = src[i];
        uint2 o;
        o.x = packh2(v.x, v.y);
        o.y = packh2(v.z, v.w);
        dst[i] = o;
    }
}
// Prepass: fp32 -> (x*256) fp16 hi/lo
__global__ __launch_bounds__(256) void convert_split_f16s(const float4* __restrict__ src,
                                                          uint2* __restrict__ hi,
                                                          uint2* __restrict__ lo, int n4)
{
    for (int i = blockIdx.x * blockDim.x + threadIdx.x; i < n4; i += gridDim.x * blockDim.x) {
        float4 v = src[i];
        v.x *= WSC; v.y *= WSC; v.z *= WSC; v.w *= WSC;
        __half h0 = __float2half(v.x), h1 = __float2half(v.y);
        __half h2 = __float2half(v.z), h3 = __float2half(v.w);
        __half l0 = __float2half(v.x - __half2float(h0));
        __half l1 = __float2half(v.y - __half2float(h1));
        __half l2 = __float2half(v.z - __half2float(h2));
        __half l3 = __float2half(v.w - __half2float(h3));
        uint2 H, L;
        __half2 t;
        t = __halves2half2(h0, h1); H.x = *(uint32_t*)&t;
        t = __halves2half2(h2, h3); H.y = *(uint32_t*)&t;
        t = __halves2half2(l0, l1); L.x = *(uint32_t*)&t;
        t = __halves2half2(l2, l3); L.y = *(uint32_t*)&t;
        hi[i] = H;
        lo[i] = L;
    }
}

// Tile offset: two 64B k-rows packed per 128B SMEM line, SW128 swizzle (GEMM tiles).
__device__ __forceinline__ uint32_t toff(int r, int c) {
    uint32_t o = ((uint32_t)(r >> 1) << 7) | ((uint32_t)(r & 1) << 6) | ((uint32_t)c << 4);
    return o ^ ((o >> 3) & 0x70);
}
// 128B-row SW128 swizzle (attention tiles)
__device__ __forceinline__ uint32_t soff(int r, int c) {
    uint32_t o = (uint32_t)r * 128 + (uint32_t)c * 16;
    return o ^ ((o >> 3) & 0x70);
}

// ---------------------------------------------------------------------------
// fp16 GEMM NT, asymmetric split: C[m,n] = (1/256) * sum_k A[m,k]*(Bh+Bl)[n,k]
// A fp16 single; B = weights*256 split hi/lo. K=1024.
// 128x128 CTA tile, BK=32, 8 warps (2m x 4n), warp tile 64x32.
// SMEM per buffer: A 8K | Bh 8K | Bl 8K = 24KB, double buffered = 48KB.
// MODE 0: C = fp32 out (proj).  MODE 1: QKV scatter epilogue.
// ---------------------------------------------------------------------------
#define GSMEM 49152

template <int MODE>
__global__ __launch_bounds__(256) void gemm_f16(const __half* __restrict__ A,
                                                const __half* __restrict__ Bh,
                                                const __half* __restrict__ Bl,
                                                float* __restrict__ C, int N)
{
    extern __shared__ __align__(1024) uint8_t smem[];
    const uint32_t sb = smem_u32(smem);

    const int tid = threadIdx.x;
    const int lane = tid & 31;
    const int wid = tid >> 5;
    const int wm = wid & 1;
    const int wn = wid >> 1;
    const int bm = blockIdx.y * 128;
    const int bn = blockIdx.x * 128;

    const int idx0 = tid * 2;
    const int m0 = idx0 >> 2, c0 = idx0 & 3;
    const int m1 = (idx0 + 1) >> 2, c1 = (idx0 + 1) & 3;
    const uint32_t so0 = toff(m0, c0);
    const uint32_t so1 = toff(m1, c1);

    const __half* pA0 = A + (size_t)(bm + m0) * 1024 + c0 * 8;
    const __half* pA1 = A + (size_t)(bm + m1) * 1024 + c1 * 8;
    const __half* pBh0 = Bh + (size_t)(bn + m0) * 1024 + c0 * 8;
    const __half* pBh1 = Bh + (size_t)(bn + m1) * 1024 + c1 * 8;
    const __half* pBl0 = Bl + (size_t)(bn + m0) * 1024 + c0 * 8;
    const __half* pBl1 = Bl + (size_t)(bn + m1) * 1024 + c1 * 8;

    const int a_row = wm * 64 + (lane & 15);
    const int a_k16 = lane >> 4;
    const int b_row = wn * 32 + (lane & 7) + ((lane >> 4) & 1) * 8;
    const int b_k16 = (lane >> 3) & 1;

    float acc[4][4][4] = {};

    {
        cp16(sb + so0, pA0);           cp16(sb + so1, pA1);
        cp16(sb + 8192 + so0, pBh0);   cp16(sb + 8192 + so1, pBh1);
        cp16(sb + 16384 + so0, pBl0);  cp16(sb + 16384 + so1, pBl1);
        CP_COMMIT();
    }

    for (int kc = 0; kc < 32; kc++) {
        const uint32_t buf = sb + (kc & 1) * 24576;
        if (kc < 31) {
            const uint32_t nbuf = sb + ((kc + 1) & 1) * 24576;
            const int ko = (kc + 1) * 32;
            cp16(nbuf + so0, pA0 + ko);           cp16(nbuf + so1, pA1 + ko);
            cp16(nbuf + 8192 + so0, pBh0 + ko);   cp16(nbuf + 8192 + so1, pBh1 + ko);
            cp16(nbuf + 16384 + so0, pBl0 + ko);  cp16(nbuf + 16384 + so1, pBl1 + ko);
            CP_COMMIT();
            CP_WAIT(1);
        } else {
            CP_WAIT(0);
        }
        __syncthreads();

#pragma unroll
        for (int ks = 0; ks < 2; ks++) {
            uint32_t a[4][4], bh[4][2], bl[4][2];
#pragma unroll
            for (int mt = 0; mt < 4; mt++) {
                const uint32_t off = toff(a_row + mt * 16, ks * 2 + a_k16);
                ldm_x4(a[mt], buf + off);
            }
#pragma unroll
            for (int nt2 = 0; nt2 < 2; nt2++) {
                const uint32_t off = toff(b_row + nt2 * 16, ks * 2 + b_k16);
                uint32_t rh[4], rl[4];
                ldm_x4(rh, buf + 8192 + off);
                ldm_x4(rl, buf + 16384 + off);
                bh[nt2 * 2][0] = rh[0]; bh[nt2 * 2][1] = rh[1];
                bh[nt2 * 2 + 1][0] = rh[2]; bh[nt2 * 2 + 1][1] = rh[3];
                bl[nt2 * 2][0] = rl[0]; bl[nt2 * 2][1] = rl[1];
                bl[nt2 * 2 + 1][0] = rl[2]; bl[nt2 * 2 + 1][1] = rl[3];
            }
#pragma unroll
            for (int mt = 0; mt < 4; mt++)
#pragma unroll
                for (int nt = 0; nt < 4; nt++) {
                    mma_f16(acc[mt][nt], a[mt], bh[nt]);
                    mma_f16(acc[mt][nt], a[mt], bl[nt]);
                }
        }
        __syncthreads();
    }

    if (MODE == 0) {
#pragma unroll
        for (int mt = 0; mt < 4; mt++) {
            const int r0 = bm + wm * 64 + mt * 16 + (lane >> 2);
#pragma unroll
            for (int nt = 0; nt < 4; nt++) {
                const int c = bn + wn * 32 + nt * 8 + (lane & 3) * 2;
                float2 v0 = {acc[mt][nt][0] * WSCI, acc[mt][nt][1] * WSCI};
                float2 v1 = {acc[mt][nt][2] * WSCI, acc[mt][nt][3] * WSCI};
                *(float2*)(C + (size_t)r0 * N + c) = v0;
                *(float2*)(C + (size_t)(r0 + 8) * N + c) = v1;
            }
        }
    } else {
        // QKV scatter: row=token, col in [0,3072)
#pragma unroll
        for (int mt = 0; mt < 4; mt++) {
            const int row = bm + wm * 64 + mt * 16 + (lane >> 2);
#pragma unroll
            for (int nt = 0; nt < 4; nt++) {
                const int c = bn + wn * 32 + nt * 8 + (lane & 3) * 2;
                const int which = c >> 10;
                const int hh = (c >> 6) & 15;
                const int d = c & 63;
#pragma unroll
                for (int half = 0; half < 2; half++) {
                    const int r = row + half * 8;
                    const int bb = r >> 11;
                    const int s = r & 2047;
                    const size_t idx = (((size_t)(bb * 16 + hh)) * SS + s) * 64 + d;
                    float v0 = acc[mt][nt][half * 2] * WSCI;
                    float v1 = acc[mt][nt][half * 2 + 1] * WSCI;
                    if (which == 0) {
                        store_split_bf16(g_qh, g_ql, idx, v0 * QSCALE, v1 * QSCALE);
                    } else if (which == 1) {
                        store_split_bf16(g_kh, g_kl, idx, v0, v1);
                    } else {
                        store_split_f16(g_vh, g_vl, idx, v0, v1);
                    }
                }
            }
        }
    }
}

// ---------------------------------------------------------------------------
// Flash attention on mma.sync (validated in R5).
// SMEM: Qh 16K | Ql 16K | K bufs 2x(8K+8K) | V bufs 2x(8K+8K) = 96KB.
// ---------------------------------------------------------------------------
#define ASMEM 98304

__device__ __forceinline__ void attn_load_kv(uint32_t sb, size_t bh, int kt, int buf, int tid)
{
#pragma unroll
    for (int i = 0; i < 8; i++) {
        const int id = tid + 256 * i;
        const int t = id >> 9;        // 0 Kh,1 Kl,2 Vh,3 Vl
        const int w = id & 511;
        const int r = w >> 3, c = w & 7;
        const uint32_t swz = soff(r, c);
        const size_t gidx = (bh * SS + (size_t)kt * 64 + r) * 64 + c * 8;
        uint32_t dst;
        const void* src;
        if (t == 0)      { dst = sb + 32768 + buf * 16384 + swz;        src = g_kh + gidx; }
        else if (t == 1) { dst = sb + 32768 + buf * 16384 + 8192 + swz; src = g_kl + gidx; }
        else if (t == 2) { dst = sb + 65536 + buf * 16384 + swz;        src = g_vh + gidx; }
        else             { dst = sb + 65536 + buf * 16384 + 8192 + swz; src = g_vl + gidx; }
        cp16(dst, src);
    }
}

__global__ __launch_bounds__(256) void attn_mma()
{
    extern __shared__ __align__(1024) uint8_t sm[];
    const uint32_t sb = smem_u32(sm);
    const int qt = (int)gridDim.x - 1 - (int)blockIdx.x;  // heavy tiles first
    const int h = blockIdx.y;
    const int b = blockIdx.z;
    const int tid = threadIdx.x;
    const int lane = tid & 31;
    const int wid = tid >> 5;
    const size_t bh = (size_t)(b * HH + h);
    const int nkt = 2 * qt + 2;

#pragma unroll
    for (int i = 0; i < 8; i++) {
        const int id = tid + 256 * i;
        const int t = id >> 10;       // 0 Qh, 1 Ql
        const int w = id & 1023;
        const int r = w >> 3, c = w & 7;
        const uint32_t dst = sb + t * 16384 + soff(r, c);
        const size_t gidx = (bh * SS + (size_t)qt * 128 + r) * 64 + c * 8;
        cp16(dst, t == 0 ? (const void*)(g_qh + gidx) : (const void*)(g_ql + gidx));
    }
    attn_load_kv(sb, bh, 0, 0, tid);
    CP_COMMIT();
    attn_load_kv(sb, bh, 1, 1, tid);
    CP_COMMIT();

    float m1 = -CUDART_INF_F, m2 = -CUDART_INF_F;
    float o[8][4] = {};
    float lac[4] = {};
    const uint32_t ones2[2] = {0x3C003C00u, 0x3C003C00u};

    const int rg1 = qt * 128 + wid * 16 + (lane >> 2);

    for (int kt = 0; kt < nkt; kt++) {
        CP_WAIT(1);
        __syncthreads();

        const uint32_t kb = sb + 32768 + (kt & 1) * 16384;
        const uint32_t vb = sb + 65536 + (kt & 1) * 16384;

        const bool skipall = (kt == 2 * qt + 1) && (wid < 4);
        if (!skipall) {
            float s[8][4];
#pragma unroll
            for (int nt = 0; nt < 8; nt++)
#pragma unroll
                for (int j = 0; j < 4; j++) s[nt][j] = 0.f;

#pragma unroll
            for (int ks = 0; ks < 4; ks++) {
                uint32_t qa[4], ql[4];
                const uint32_t offA = soff(wid * 16 + (lane & 15), ks * 2 + (lane >> 4));
                ldm_x4(qa, sb + offA);
                ldm_x4(ql, sb + 16384 + offA);
#pragma unroll
                for (int nb = 0; nb < 4; nb++) {
                    const uint32_t offB = soff(nb * 16 + (lane & 7) + ((lane >> 4) & 1) * 8,
                                               ks * 2 + ((lane >> 3) & 1));
                    uint32_t rh[4], rl[4];
                    ldm_x4(rh, kb + offB);
                    ldm_x4(rl, kb + 8192 + offB);
                    mma_bf16(s[nb * 2], qa, rh);
                    mma_bf16(s[nb * 2], qa, rl);
                    mma_bf16(s[nb * 2], ql, rh);
                    mma_bf16(s[nb * 2 + 1], qa, rh + 2);
                    mma_bf16(s[nb * 2 + 1], qa, rl + 2);
                    mma_bf16(s[nb * 2 + 1], ql, rh + 2);
                }
            }

            const bool domask = (kt == 2 * qt && wid < 4) || (kt == 2 * qt + 1 && wid >= 4);
            if (domask) {
#pragma unroll
                for (int nt = 0; nt < 8; nt++) {
                    const int cg = kt * 64 + nt * 8 + (lane & 3) * 2;
#pragma unroll
                    for (int j = 0; j < 4; j++) {
                        const int col = cg + (j & 1);
                        const int row = rg1 + ((j >> 1) << 3);
                        if (col > row) s[nt][j] = -1e30f;
                    }
                }
            }

            float t1 = -CUDART_INF_F, t2 = -CUDART_INF_F;
#pragma unroll
            for (int nt = 0; nt < 8; nt++) {
                t1 = fmaxf(t1, fmaxf(s[nt][0], s[nt][1]));
                t2 = fmaxf(t2, fmaxf(s[nt][2], s[nt][3]));
            }
            t1 = fmaxf(t1, __shfl_xor_sync(0xffffffffu, t1, 1));
            t1 = fmaxf(t1, __shfl_xor_sync(0xffffffffu, t1, 2));
            t2 = fmaxf(t2, __shfl_xor_sync(0xffffffffu, t2, 1));
            t2 = fmaxf(t2, __shfl_xor_sync(0xffffffffu, t2, 2));
            const float mn1 = fmaxf(m1, t1);
            const float mn2 = fmaxf(m2, t2);
            const float cr1 = ex2f(m1 - mn1);
            const float cr2 = ex2f(m2 - mn2);
            m1 = mn1; m2 = mn2;

            uint32_t p1[8], p2[8];
#pragma unroll
            for (int nt = 0; nt < 8; nt++) {
                p1[nt] = packh2(ex2f(s[nt][0] - mn1), ex2f(s[nt][1] - mn1));
                p2[nt] = packh2(ex2f(s[nt][2] - mn2), ex2f(s[nt][3] - mn2));
            }
#pragma unroll
            for (int nt = 0; nt < 8; nt++) {
                o[nt][0] *= cr1; o[nt][1] *= cr1;
                o[nt][2] *= cr2; o[nt][3] *= cr2;
            }
            lac[0] *= cr1; lac[1] *= cr1; lac[2] *= cr2; lac[3] *= cr2;

#pragma unroll
            for (int ks = 0; ks < 4; ks++) {
                uint32_t A[4] = {p1[ks * 2], p2[ks * 2], p1[ks * 2 + 1], p2[ks * 2 + 1]};
#pragma unroll
                for (int nb = 0; nb < 4; nb++) {
                    const uint32_t offV = soff(ks * 16 + (lane & 15), nb * 2 + (lane >> 4));
                    uint32_t vh[4], vl[4];
                    ldm_x4_t(vh, vb + offV);
                    ldm_x4_t(vl, vb + 8192 + offV);
                    mma_f16(o[nb * 2], A, vh);
                    mma_f16(o[nb * 2], A, vl);
                    mma_f16(o[nb * 2 + 1], A, vh + 2);
                    mma_f16(o[nb * 2 + 1], A, vl + 2);
                }
                mma_f16(lac, A, ones2);
            }
        }

        __syncthreads();
        if (kt + 2 < nkt) attn_load_kv(sb, bh, kt + 2, kt & 1, tid);
        CP_COMMIT();
    }

    // epilogue: normalize, write single fp16 [token][1024]
    const float inv1 = 1.f / lac[0];
    const float inv2 = 1.f / lac[2];
    const size_t tok1 = (size_t)(b * SS + qt * 128 + wid * 16 + (lane >> 2));
#pragma unroll
    for (int nt = 0; nt < 8; nt++) {
        const int col = h * 64 + nt * 8 + (lane & 3) * 2;
        const uint32_t u1 = packh2(o[nt][0] * inv1, o[nt][1] * inv1);
        const uint32_t u2 = packh2(o[nt][2] * inv2, o[nt][3] * inv2);
        *(uint32_t*)(g_af + tok1 * 1024 + col) = u1;
        *(uint32_t*)(g_af + (tok1 + 8) * 1024 + col) = u2;
    }
}

// ---------------------------------------------------------------------------
extern "C" void kernel_launch(void* const* d_in, const int* in_sizes, int n_in,
                              void* d_out, int out_size)
{
    const float* x    = (const float*)d_in[0];  // [2,2048,1024]
    const float* wqkv = (const float*)d_in[1];  // [3072,1024]
    const float* wo   = (const float*)d_in[2];  // [1024,1024]
    float* out = (float*)d_out;                 // [2,2048,1024]

    __half *xf, *wh, *wl, *woh, *wol, *af;
    cudaGetSymbolAddress((void**)&xf, g_xf);
    cudaGetSymbolAddress((void**)&wh, g_wh);
    cudaGetSymbolAddress((void**)&wl, g_wl);
    cudaGetSymbolAddress((void**)&woh, g_woh);
    cudaGetSymbolAddress((void**)&wol, g_wol);
    cudaGetSymbolAddress((void**)&af, g_af);

    cudaFuncSetAttribute(gemm_f16<0>, cudaFuncAttributeMaxDynamicSharedMemorySize, GSMEM);
    cudaFuncSetAttribute(gemm_f16<1>, cudaFuncAttributeMaxDynamicSharedMemorySize, GSMEM);
    cudaFuncSetAttribute(attn_mma, cudaFuncAttributeMaxDynamicSharedMemorySize, ASMEM);

    // Prepass conversions
    convert_f16<<<512, 256>>>((const float4*)x, (uint2*)xf, 4096 * 1024 / 4);
    convert_split_f16s<<<512, 256>>>((const float4*)wqkv, (uint2*)wh, (uint2*)wl, 3072 * 1024 / 4);
    convert_split_f16s<<<256, 256>>>((const float4*)wo, (uint2*)woh, (uint2*)wol, 1024 * 1024 / 4);

    // QKV = x @ wqkv^T with scatter epilogue -> g_qh/ql/kh/kl/vh/vl
    gemm_f16<1><<<dim3(3072 / 128, 4096 / 128), 256, GSMEM>>>(xf, wh, wl, nullptr, 3072);

    // Attention -> g_af (fp16)
    attn_mma<<<dim3(SS / 128, HH, BB), 256, ASMEM>>>();

    // out = attn @ wo^T
    gemm_f16<0><<<dim3(1024 / 128, 4096 / 128), 256, GSMEM>>>(af, woh, wol, out, 1024);
}